// round 9
// baseline (speedup 1.0000x reference)
#include <cuda_runtime.h>
#include <math.h>

#define BB   32
#define TT   12
#define NN_  200
#define HH   128
#define DHH  64
#define DIN_ 2
#define MM   5
#define NB   6400
#define HH2  256
#define D0E  130
#define D0D  129
#define D1_  256
#define NN2  40000
#define CAP1 200
#define CAP2 32
#define CT   32

#define SZ_EG0 (D0E*MM*HH2)
#define SZ_EC0 (D0E*MM*HH)
#define SZ_EG1 (D1_*MM*HH2)
#define SZ_EC1 (D1_*MM*HH)
#define SZ_DG0 (D0D*MM*HH2)
#define SZ_DC0 (D0D*MM*HH)
#define OFF_EG0 0
#define OFF_EC0 (OFF_EG0+SZ_EG0)
#define OFF_EG1 (OFF_EC0+SZ_EC0)
#define OFF_EC1 (OFF_EG1+SZ_EG1)
#define OFF_DG0 (OFF_EC1+SZ_EC1)
#define OFF_DC0 (OFF_DG0+SZ_DG0)
#define OFF_DG1 (OFF_DC0+SZ_DC0)
#define OFF_DC1 (OFF_DG1+SZ_EG1)
#define WRE_TOTAL (OFF_DC1+SZ_EC1)

__device__ float g_WhhT[HH*3*HH];
__device__ float g_Wre[WRE_TOTAL];
__device__ float g_hgru[NB*HH];
__device__ float g_outs[TT*NB*HH];
__device__ float g_att[TT*NB];
__device__ float g_pooled[NB*HH];
__device__ float g_keym[NB*DHH];
__device__ float g_qm[NB*DHH];
__device__ float g_adj[BB*NN2];
__device__ float g_rowinv[NB];
__device__ float g_colinv[NB];
__device__ int   g_s1i[(size_t)NB*CAP1];
__device__ float g_s1v[(size_t)NB*CAP1];
__device__ int   g_s1c[NB];
__device__ int   g_s2i[(size_t)NB*CAP2];
__device__ float g_s2v[(size_t)NB*CAP2];
__device__ int   g_s2c[NB];
__device__ float g_xm[(size_t)MM*NB*256];
__device__ float g_ru[NB*HH2];
__device__ float g_h0[NB*HH];
__device__ float g_h1[NB*HH];
__device__ float g_go[NB];

__device__ __forceinline__ float sigf(float x){ return 1.f/(1.f+expf(-x)); }

__device__ __forceinline__ unsigned long long pk2(float x){
    unsigned long long r; asm("mov.b64 %0,{%1,%1};":"=l"(r):"f"(x)); return r;
}
__device__ __forceinline__ unsigned long long f2fma(unsigned long long a, unsigned long long b, unsigned long long c){
    unsigned long long d; asm("fma.rn.f32x2 %0,%1,%2,%3;":"=l"(d):"l"(a),"l"(b),"l"(c)); return d;
}
__device__ __forceinline__ float2 up2(unsigned long long v){
    float2 f; asm("mov.b64 {%0,%1},%2;":"=f"(f.x),"=f"(f.y):"l"(v)); return f;
}

__global__ void zero_k(float* p, int n){
    int i = blockIdx.x*blockDim.x+threadIdx.x;
    if (i < n) p[i] = 0.f;
}

__global__ void transpose_whh(const float* __restrict__ Whh){
    int idx = blockIdx.x*blockDim.x+threadIdx.x;
    if (idx >= 3*HH*HH) return;
    int j = idx/HH, k = idx%HH;
    g_WhhT[k*(3*HH)+j] = Whh[j*HH+k];
}

__global__ void reorder_w(const float* __restrict__ W, float* __restrict__ Wre, int D, int OUT){
    int idx = blockIdx.x*blockDim.x+threadIdx.x;
    if (idx >= D*MM*OUT) return;
    int o = idx%OUT; int t2 = idx/OUT; int d = t2%D; int m = t2/D;
    Wre[idx] = W[(d*MM+m)*OUT+o];
}

// ---------------- GRU: 8 rows per block ----------------
__global__ void __launch_bounds__(128) gru_step(
    const float* __restrict__ e, int t,
    const float* __restrict__ Wih, const float* __restrict__ bih,
    const float* __restrict__ bhh, float* __restrict__ h, float* __restrict__ outs)
{
    __shared__ float hs[8][HH];
    int tid = threadIdx.x;
    int r0 = blockIdx.x*8;
    #pragma unroll
    for (int q = 0; q < 8; q++) hs[q][tid] = h[(r0+q)*HH+tid];
    __syncthreads();
    float a0[8], a1[8], a2[8];
    #pragma unroll
    for (int q = 0; q < 8; q++){ a0[q]=0.f; a1[q]=0.f; a2[q]=0.f; }
    for (int k = 0; k < HH; k++){
        float w0 = g_WhhT[k*384+tid];
        float w1 = g_WhhT[k*384+HH+tid];
        float w2 = g_WhhT[k*384+2*HH+tid];
        #pragma unroll
        for (int q = 0; q < 8; q++){
            float hk = hs[q][k];
            a0[q] += hk*w0; a1[q] += hk*w1; a2[q] += hk*w2;
        }
    }
    float b0 = bhh[tid], b1 = bhh[HH+tid], b2 = bhh[2*HH+tid];
    float wi0a=Wih[tid*2], wi0b=Wih[tid*2+1];
    float wi1a=Wih[(HH+tid)*2], wi1b=Wih[(HH+tid)*2+1];
    float wi2a=Wih[(2*HH+tid)*2], wi2b=Wih[(2*HH+tid)*2+1];
    float bi0=bih[tid], bi1=bih[HH+tid], bi2=bih[2*HH+tid];
    #pragma unroll
    for (int q = 0; q < 8; q++){
        int r = r0+q;
        int n = r >> 5, b = r & 31;
        const float* x = e + (((size_t)b*TT+t)*NN_+n)*DIN_;
        float x0 = x[0], x1 = x[1];
        float ir = x0*wi0a + x1*wi0b + bi0;
        float iz = x0*wi1a + x1*wi1b + bi1;
        float ig = x0*wi2a + x1*wi2b + bi2;
        float rg = sigf(ir + a0[q] + b0);
        float zg = sigf(iz + a1[q] + b1);
        float ng = tanhf(ig + rg*(a2[q] + b2));
        float hn = (1.f-zg)*ng + zg*hs[q][tid];
        h[r*HH+tid] = hn;
        outs[(((size_t)t*NN_+n)*BB+b)*HH+tid] = hn;
    }
}

__global__ void att_score(const float* __restrict__ outs, const float* __restrict__ attW,
                          const float* __restrict__ attb, const float* __restrict__ wlc,
                          float* __restrict__ z)
{
    int warp = threadIdx.x >> 5, lane = threadIdx.x & 31;
    int row = blockIdx.x*8 + warp;
    if (row >= TT*NB) return;
    const float* o = outs + (size_t)row*HH;
    float o0=o[lane], o1=o[32+lane], o2=o[64+lane], o3=o[96+lane];
    float acc = 0.f;
    for (int d = 0; d < DHH; d++){
        const float* w = attW + d*HH;
        float p = w[lane]*o0 + w[32+lane]*o1 + w[64+lane]*o2 + w[96+lane]*o3;
        p += __shfl_xor_sync(0xffffffffu,p,16);
        p += __shfl_xor_sync(0xffffffffu,p,8);
        p += __shfl_xor_sync(0xffffffffu,p,4);
        p += __shfl_xor_sync(0xffffffffu,p,2);
        p += __shfl_xor_sync(0xffffffffu,p,1);
        acc += wlc[d]*fmaxf(p + attb[d], 0.f);
    }
    if (lane == 0) z[row] = acc;
}

__global__ void att_softmax_t(float* __restrict__ z){
    int idx = blockIdx.x*blockDim.x+threadIdx.x;
    if (idx >= NB) return;
    float v[TT]; float m = -3.0e38f;
    #pragma unroll
    for (int t = 0; t < TT; t++){ v[t] = z[t*NB+idx]; m = fmaxf(m, v[t]); }
    float s = 0.f;
    #pragma unroll
    for (int t = 0; t < TT; t++){ v[t] = expf(v[t]-m); s += v[t]; }
    float inv = 1.f/s;
    #pragma unroll
    for (int t = 0; t < TT; t++) z[t*NB+idx] = v[t]*inv;
}

__global__ void pooled_k(const float* __restrict__ outs, const float* __restrict__ att,
                         float* __restrict__ pooled)
{
    int idx = blockIdx.x*blockDim.x+threadIdx.x;
    if (idx >= NB*HH) return;
    int hh = idx & 127;
    int r = idx >> 7;
    int b = r/NN_, n = r%NN_;
    float acc = 0.f;
    #pragma unroll
    for (int t = 0; t < TT; t++)
        acc += outs[(((size_t)t*NN_+n)*BB+b)*HH+hh] * att[t*NB + n*BB + b];
    pooled[idx] = acc;
}

__global__ void keyqm_k(const float* __restrict__ pooled, const float* __restrict__ wkey,
                        const float* __restrict__ wq, float* __restrict__ keym,
                        float* __restrict__ qm)
{
    int idx = blockIdx.x*blockDim.x+threadIdx.x;
    if (idx >= NB*DHH) return;
    int d = idx % DHH;
    int r = idx / DHH;
    float ak = 0.f, aq = 0.f;
    for (int hh = 0; hh < HH; hh++){
        float p = pooled[r*HH+hh];
        ak += p*wkey[hh*DHH+d];
        aq += p*wq[hh*DHH+d];
    }
    keym[idx] = ak; qm[idx] = aq;
}

__global__ void __launch_bounds__(256) attn_row(
    const float* __restrict__ keym, const float* __restrict__ qm,
    const int* __restrict__ topk, float* __restrict__ adj, float* __restrict__ rowinv)
{
    __shared__ float krow[DHH];
    __shared__ float red[256];
    __shared__ float srt[256];
    const float inv_sqrt_h = 0.08838834764831845f;
    int b = blockIdx.x/NN_, i = blockIdx.x%NN_;
    int tid = threadIdx.x;
    if (tid < DHH) krow[tid] = keym[(b*NN_+i)*DHH+tid];
    __syncthreads();
    float a = -3.0e38f;
    if (tid < NN_){
        const float* q = qm + (b*NN_+tid)*DHH;
        float acc = 0.f;
        #pragma unroll 8
        for (int d = 0; d < DHH; d++) acc += krow[d]*q[d];
        a = acc*inv_sqrt_h;
    }
    red[tid] = a; __syncthreads();
    for (int s = 128; s > 0; s >>= 1){
        if (tid < s) red[tid] = fmaxf(red[tid], red[tid+s]);
        __syncthreads();
    }
    float mx = red[0]; __syncthreads();
    float e = (tid < NN_) ? expf(a-mx) : 0.f;
    red[tid] = e; __syncthreads();
    for (int s = 128; s > 0; s >>= 1){
        if (tid < s) red[tid] += red[tid+s];
        __syncthreads();
    }
    float sum = red[0]; __syncthreads();
    float at = (tid < NN_) ? e/sum : 0.f;
    srt[tid] = (tid < NN_) ? at : -3.0e38f;
    for (int k2 = 2; k2 <= 256; k2 <<= 1){
        for (int j = k2>>1; j > 0; j >>= 1){
            __syncthreads();
            int ixj = tid ^ j;
            if (ixj > tid){
                float x = srt[tid], y = srt[ixj];
                bool asc = ((tid & k2) == 0);
                if ((x > y) == asc){ srt[tid] = y; srt[ixj] = x; }
            }
        }
    }
    __syncthreads();
    int tk = topk ? *topk : 20;
    float kth = srt[256-tk];
    float ad = (tid < NN_ && at >= kth) ? at : 0.f;
    if (tid == i) ad += 1.f;
    if (tid < NN_) adj[(size_t)b*NN2 + i*NN_ + tid] = ad;
    __syncthreads();
    red[tid] = (tid < NN_) ? ad : 0.f;
    __syncthreads();
    for (int s = 128; s > 0; s >>= 1){
        if (tid < s) red[tid] += red[tid+s];
        __syncthreads();
    }
    if (tid == 0){
        float rs = red[0];
        rowinv[b*NN_+i] = (rs == 0.f) ? 0.f : 1.f/rs;
    }
}

__global__ void colsum_k(const float* __restrict__ adj, float* __restrict__ colinv){
    int idx = blockIdx.x*blockDim.x+threadIdx.x;
    if (idx >= NB) return;
    int b = idx/NN_, j = idx%NN_;
    float s = 0.f;
    for (int i = 0; i < NN_; i++) s += adj[(size_t)b*NN2 + i*NN_ + j];
    colinv[idx] = (s == 0.f) ? 0.f : 1.f/s;
}

__global__ void csr_build(const float* __restrict__ adj, const float* __restrict__ rowinv,
                          const float* __restrict__ colinv,
                          int* __restrict__ s1i, float* __restrict__ s1v, int* __restrict__ s1c,
                          int* __restrict__ s2i, float* __restrict__ s2v, int* __restrict__ s2c)
{
    int r = blockIdx.x*blockDim.x+threadIdx.x;
    if (r >= NB) return;
    int b = r/NN_, i = r%NN_;
    const float* A = adj + (size_t)b*NN2;
    int c2 = 0;
    for (int j = 0; j < NN_; j++){
        float a = A[i*NN_+j];
        if (a != 0.f && c2 < CAP2){
            s2i[(size_t)r*CAP2+c2] = j;
            s2v[(size_t)r*CAP2+c2] = a*colinv[b*NN_+j];
            c2++;
        }
    }
    s2c[r] = c2;
    int c1 = 0;
    for (int j = 0; j < NN_; j++){
        float a = A[j*NN_+i];
        if (a != 0.f){
            s1i[(size_t)r*CAP1+c1] = j;
            s1v[(size_t)r*CAP1+c1] = a*rowinv[b*NN_+j];
            c1++;
        }
    }
    s1c[r] = c1;
}

// concat [x, (r*)h] into plane0, columns [dstart, Dc)
__global__ void cat_k(const float* __restrict__ xb, int xbstr, int xnstr, int Dx,
                      const float* __restrict__ h, const float* __restrict__ ru,
                      float* __restrict__ plane0, int Dc, int dstart)
{
    int w = Dc - dstart;
    int idx = blockIdx.x*blockDim.x+threadIdx.x;
    if (idx >= NB*w) return;
    int d = dstart + idx % w;
    int r = idx / w;
    int b = r/NN_, n = r%NN_;
    float v;
    if (d < Dx){
        v = xb[(size_t)b*xbstr + n*xnstr + d];
    } else {
        int dh = d - Dx;
        v = h[r*HH + dh];
        if (ru) v *= ru[r*HH2 + dh];
    }
    plane0[(size_t)r*Dc + d] = v;
}

// Fused Chebyshev spmm: block = (col-tile, batch, support).
// Loads X0 tile (200 x 32) into smem, computes Y1 = S@X0 (kept in regs + written
// to smem + gmem), then Y2 = 2*S@Y1 - X0, both steps in one launch. L2 gather
// traffic drops ~21x vs per-row gather spmm.
__global__ void __launch_bounds__(256) cheb_k(
    float* __restrict__ xm, int D, int dstart)
{
    __shared__ float Xs[NN_][CT+1];
    int ct = blockIdx.x, b = blockIdx.y, z = blockIdx.z;
    size_t PL = (size_t)NB*D;
    const float* X0g = xm;
    float* Y1g = xm + (z==0 ? 1 : 3)*PL;
    float* Y2g = xm + (z==0 ? 2 : 4)*PL;
    int d0 = dstart + ct*CT;
    int tid = threadIdx.x;
    int dl = tid & 31, wid = tid >> 5;   // 8 warps, 25 rows each
    int d = d0 + dl;
    bool dok = (d < D);

    for (int idx = tid; idx < NN_*CT; idx += 256){
        int col = idx & (CT-1), row = idx >> 5;
        int dd = d0 + col;
        Xs[row][col] = (dd < D) ? X0g[(size_t)(b*NN_+row)*D + dd] : 0.f;
    }
    __syncthreads();

    const int* Ibase; const float* Vbase; const int* Cbase; int cap;
    if (z == 0){ Ibase = g_s1i; Vbase = g_s1v; Cbase = g_s1c; cap = CAP1; }
    else       { Ibase = g_s2i; Vbase = g_s2v; Cbase = g_s2c; cap = CAP2; }

    float y1[25];
    #pragma unroll
    for (int q = 0; q < 25; q++){
        int i = wid + q*8;
        int r = b*NN_ + i;
        const int* Ip = Ibase + (size_t)r*cap;
        const float* Vp = Vbase + (size_t)r*cap;
        int cnt = Cbase[r];
        float acc = 0.f;
        for (int k = 0; k < cnt; k++)
            acc += Vp[k]*Xs[Ip[k]][dl];
        y1[q] = acc;
    }
    __syncthreads();
    #pragma unroll
    for (int q = 0; q < 25; q++){
        int i = wid + q*8;
        Xs[i][dl] = y1[q];
        if (dok) Y1g[(size_t)(b*NN_+i)*D + d] = y1[q];
    }
    __syncthreads();
    #pragma unroll
    for (int q = 0; q < 25; q++){
        int i = wid + q*8;
        int r = b*NN_ + i;
        const int* Ip = Ibase + (size_t)r*cap;
        const float* Vp = Vbase + (size_t)r*cap;
        int cnt = Cbase[r];
        float acc = 0.f;
        for (int k = 0; k < cnt; k++)
            acc += Vp[k]*Xs[Ip[k]][dl];
        if (dok) Y2g[(size_t)r*D + d] = 2.f*acc - X0g[(size_t)r*D + d];
    }
}

// 64x64-tile GEMM over 5 planes, f32x2 packed FMA; fused epilogue.
__global__ void __launch_bounds__(256) dense_mm(
    const float* __restrict__ Xm, int D,
    const float* __restrict__ Wre, const float* __restrict__ bias,
    int OUT, float* __restrict__ C,
    const float* __restrict__ ruh, float* __restrict__ hbuf)
{
    __shared__ float As[16][64];
    __shared__ float Bs[16][64];
    int tid = threadIdx.x;
    int row0 = blockIdx.x*64, col0 = blockIdx.y*64;
    int tx = tid & 15, ty = tid >> 4;
    unsigned long long acc[4][2];
    #pragma unroll
    for (int i = 0; i < 4; i++){ acc[i][0] = 0ull; acc[i][1] = 0ull; }
    size_t PL = (size_t)NB*D;
    for (int m = 0; m < MM; m++){
        const float* Xp = Xm + m*PL;
        const float* Wp = Wre + (size_t)m*D*OUT;
        for (int k0 = 0; k0 < D; k0 += 16){
            #pragma unroll
            for (int e = 0; e < 4; e++){
                int idx = tid*4+e;
                int r = idx >> 4, kk = idx & 15;
                As[kk][r] = (k0+kk < D) ? Xp[(size_t)(row0+r)*D + k0+kk] : 0.f;
            }
            #pragma unroll
            for (int e = 0; e < 4; e++){
                int idx = tid*4+e;
                int kk = idx >> 6, nn = idx & 63;
                Bs[kk][nn] = (k0+kk < D) ? Wp[(size_t)(k0+kk)*OUT + col0+nn] : 0.f;
            }
            __syncthreads();
            #pragma unroll
            for (int kk = 0; kk < 16; kk++){
                float4 av = *reinterpret_cast<const float4*>(&As[kk][ty*4]);
                const unsigned long long* bp = reinterpret_cast<const unsigned long long*>(&Bs[kk][tx*4]);
                unsigned long long b0 = bp[0], b1 = bp[1];
                unsigned long long a;
                a = pk2(av.x); acc[0][0] = f2fma(a,b0,acc[0][0]); acc[0][1] = f2fma(a,b1,acc[0][1]);
                a = pk2(av.y); acc[1][0] = f2fma(a,b0,acc[1][0]); acc[1][1] = f2fma(a,b1,acc[1][1]);
                a = pk2(av.z); acc[2][0] = f2fma(a,b0,acc[2][0]); acc[2][1] = f2fma(a,b1,acc[2][1]);
                a = pk2(av.w); acc[3][0] = f2fma(a,b0,acc[3][0]); acc[3][1] = f2fma(a,b1,acc[3][1]);
            }
            __syncthreads();
        }
    }
    #pragma unroll
    for (int i = 0; i < 4; i++){
        int rr = row0 + ty*4 + i;
        #pragma unroll
        for (int jp = 0; jp < 2; jp++){
            float2 f = up2(acc[i][jp]);
            #pragma unroll
            for (int u2 = 0; u2 < 2; u2++){
                int cc = col0 + tx*4 + jp*2 + u2;
                float v = (u2 == 0 ? f.x : f.y) + bias[cc];
                if (hbuf){
                    float c = tanhf(v);
                    float u = ruh[(size_t)rr*HH2 + HH + cc];
                    float hold = hbuf[(size_t)rr*HH + cc];
                    hbuf[(size_t)rr*HH + cc] = u*hold + (1.f-u)*c;
                } else {
                    C[(size_t)rr*OUT + cc] = 1.f/(1.f+expf(-v));
                }
            }
        }
    }
}

__global__ void proj_k(const float* __restrict__ h1, const float* __restrict__ pw,
                       const float* __restrict__ pb, float* __restrict__ outp,
                       float* __restrict__ go)
{
    int warp = threadIdx.x >> 5, lane = threadIdx.x & 31;
    int row = blockIdx.x*8 + warp;
    if (row >= NB) return;
    const float* hr = h1 + (size_t)row*HH;
    float a = hr[lane]*pw[lane] + hr[32+lane]*pw[32+lane]
            + hr[64+lane]*pw[64+lane] + hr[96+lane]*pw[96+lane];
    a += __shfl_xor_sync(0xffffffffu,a,16);
    a += __shfl_xor_sync(0xffffffffu,a,8);
    a += __shfl_xor_sync(0xffffffffu,a,4);
    a += __shfl_xor_sync(0xffffffffu,a,2);
    a += __shfl_xor_sync(0xffffffffu,a,1);
    if (lane == 0){
        float v = a + pb[0];
        outp[row] = v;
        go[row] = v;
    }
}

extern "C" void kernel_launch(void* const* d_in, const int* in_sizes, int n_in,
                              void* d_out, int out_size)
{
    const float* enc  = (const float*)d_in[0];
    const float* Wih  = (const float*)d_in[2];
    const float* Whh  = (const float*)d_in[3];
    const float* bih  = (const float*)d_in[4];
    const float* bhh  = (const float*)d_in[5];
    const float* attW = (const float*)d_in[6];
    const float* attb = (const float*)d_in[7];
    const float* wlc  = (const float*)d_in[8];
    const float* wkey = (const float*)d_in[9];
    const float* wq   = (const float*)d_in[10];
    const float* eg0  = (const float*)d_in[11];
    const float* ebg0 = (const float*)d_in[12];
    const float* ec0  = (const float*)d_in[13];
    const float* ebc0 = (const float*)d_in[14];
    const float* eg1  = (const float*)d_in[15];
    const float* ebg1 = (const float*)d_in[16];
    const float* ec1  = (const float*)d_in[17];
    const float* ebc1 = (const float*)d_in[18];
    const float* dg0  = (const float*)d_in[19];
    const float* dbg0 = (const float*)d_in[20];
    const float* dc0  = (const float*)d_in[21];
    const float* dbc0 = (const float*)d_in[22];
    const float* dg1  = (const float*)d_in[23];
    const float* dbg1 = (const float*)d_in[24];
    const float* dc1  = (const float*)d_in[25];
    const float* dbc1 = (const float*)d_in[26];
    const float* pw   = (const float*)d_in[27];
    const float* pb   = (const float*)d_in[28];
    const int*  topk  = (n_in > 29) ? (const int*)d_in[29] : nullptr;
    float* out = (float*)d_out;

    float *wre,*hgru,*outs,*att,*pooled,*keym,*qm,*adj,*rowinv,*colinv,*xm,*rub,*h0,*h1,*go;
    int *s1i,*s1c,*s2i,*s2c; float *s1v,*s2v;
    cudaGetSymbolAddress((void**)&wre, g_Wre);
    cudaGetSymbolAddress((void**)&hgru, g_hgru);
    cudaGetSymbolAddress((void**)&outs, g_outs);
    cudaGetSymbolAddress((void**)&att, g_att);
    cudaGetSymbolAddress((void**)&pooled, g_pooled);
    cudaGetSymbolAddress((void**)&keym, g_keym);
    cudaGetSymbolAddress((void**)&qm, g_qm);
    cudaGetSymbolAddress((void**)&adj, g_adj);
    cudaGetSymbolAddress((void**)&rowinv, g_rowinv);
    cudaGetSymbolAddress((void**)&colinv, g_colinv);
    cudaGetSymbolAddress((void**)&s1i, g_s1i);
    cudaGetSymbolAddress((void**)&s1v, g_s1v);
    cudaGetSymbolAddress((void**)&s1c, g_s1c);
    cudaGetSymbolAddress((void**)&s2i, g_s2i);
    cudaGetSymbolAddress((void**)&s2v, g_s2v);
    cudaGetSymbolAddress((void**)&s2c, g_s2c);
    cudaGetSymbolAddress((void**)&xm, g_xm);
    cudaGetSymbolAddress((void**)&rub, g_ru);
    cudaGetSymbolAddress((void**)&h0, g_h0);
    cudaGetSymbolAddress((void**)&h1, g_h1);
    cudaGetSymbolAddress((void**)&go, g_go);

    transpose_whh<<<(3*HH*HH+255)/256, 256>>>(Whh);
    reorder_w<<<(SZ_EG0+255)/256, 256>>>(eg0, wre+OFF_EG0, D0E, HH2);
    reorder_w<<<(SZ_EC0+255)/256, 256>>>(ec0, wre+OFF_EC0, D0E, HH);
    reorder_w<<<(SZ_EG1+255)/256, 256>>>(eg1, wre+OFF_EG1, D1_, HH2);
    reorder_w<<<(SZ_EC1+255)/256, 256>>>(ec1, wre+OFF_EC1, D1_, HH);
    reorder_w<<<(SZ_DG0+255)/256, 256>>>(dg0, wre+OFF_DG0, D0D, HH2);
    reorder_w<<<(SZ_DC0+255)/256, 256>>>(dc0, wre+OFF_DC0, D0D, HH);
    reorder_w<<<(SZ_EG1+255)/256, 256>>>(dg1, wre+OFF_DG1, D1_, HH2);
    reorder_w<<<(SZ_EC1+255)/256, 256>>>(dc1, wre+OFF_DC1, D1_, HH);

    zero_k<<<(NB*HH+255)/256, 256>>>(hgru, NB*HH);
    for (int t = 0; t < TT; t++)
        gru_step<<<NB/8, 128>>>(enc, t, Wih, bih, bhh, hgru, outs);

    att_score<<<(TT*NB)/8, 256>>>(outs, attW, attb, wlc, att);
    att_softmax_t<<<(NB+255)/256, 256>>>(att);
    pooled_k<<<(NB*HH+255)/256, 256>>>(outs, att, pooled);
    keyqm_k<<<(NB*DHH+255)/256, 256>>>(pooled, wkey, wq, keym, qm);
    attn_row<<<BB*NN_, 256>>>(keym, qm, topk, adj, rowinv);
    colsum_k<<<(NB+255)/256, 256>>>(adj, colinv);
    csr_build<<<(NB+255)/256, 256>>>(adj, rowinv, colinv, s1i, s1v, s1c, s2i, s2v, s2c);

    auto gconv = [&](const float* xb, int xbstr, int xnstr, int Dx, float* h,
                     const float* rmul, const float* Wp, const float* bias,
                     int OUT, float* Cout, float* hfuse){
        int Dc = Dx + HH;
        int dstart = rmul ? Dx : 0;     // candidate reuses gate's x-column planes
        int w = Dc - dstart;
        cat_k<<<(NB*w+255)/256, 256>>>(xb, xbstr, xnstr, Dx, h, rmul, xm, Dc, dstart);
        dim3 cg((w+CT-1)/CT, BB, 2);
        cheb_k<<<cg, 256>>>(xm, Dc, dstart);
        dense_mm<<<dim3(NB/64, OUT/64), 256>>>(xm, Dc, Wp, bias, OUT, Cout, rmul, hfuse);
    };
    auto cell = [&](const float* xb, int xbstr, int xnstr, int Dx, float* h,
                    const float* Wg, const float* bg, const float* Wc, const float* bc){
        gconv(xb, xbstr, xnstr, Dx, h, nullptr, Wg, bg, HH2, rub, nullptr);
        gconv(xb, xbstr, xnstr, Dx, h, rub,     Wc, bc, HH,  nullptr, h);
    };

    zero_k<<<(NB*HH+255)/256, 256>>>(h0, NB*HH);
    zero_k<<<(NB*HH+255)/256, 256>>>(h1, NB*HH);
    for (int t = 0; t < TT; t++){
        cell(enc + (size_t)t*NN_*DIN_, TT*NN_*DIN_, DIN_, DIN_, h0,
             wre+OFF_EG0, ebg0, wre+OFF_EC0, ebc0);
        cell(h0, NN_*HH, HH, HH, h1,
             wre+OFF_EG1, ebg1, wre+OFF_EC1, ebc1);
    }

    zero_k<<<(NB+255)/256, 256>>>(go, NB);
    for (int t = 0; t < TT; t++){
        cell(go, NN_, 1, 1, h0,
             wre+OFF_DG0, dbg0, wre+OFF_DC0, dbc0);
        cell(h0, NN_*HH, HH, HH, h1,
             wre+OFF_DG1, dbg1, wre+OFF_DC1, dbc1);
        proj_k<<<NB/8, 256>>>(h1, pw, pb, out + (size_t)t*NB, go);
    }
    (void)in_sizes; (void)out_size;
}

// round 10
// speedup vs baseline: 1.0002x; 1.0002x over previous
#include <cuda_runtime.h>
#include <math.h>

#define BB   32
#define TT   12
#define NN_  200
#define HH   128
#define DHH  64
#define DIN_ 2
#define MM   5
#define NB   6400
#define HH2  256
#define D0E  130
#define D0D  129
#define D1_  256
#define NN2  40000
#define CAP1 200
#define CAP2 32
#define CT   32

#define SZ_EG0 (D0E*MM*HH2)
#define SZ_EC0 (D0E*MM*HH)
#define SZ_EG1 (D1_*MM*HH2)
#define SZ_EC1 (D1_*MM*HH)
#define SZ_DG0 (D0D*MM*HH2)
#define SZ_DC0 (D0D*MM*HH)
#define OFF_EG0 0
#define OFF_EC0 (OFF_EG0+SZ_EG0)
#define OFF_EG1 (OFF_EC0+SZ_EC0)
#define OFF_EC1 (OFF_EG1+SZ_EG1)
#define OFF_DG0 (OFF_EC1+SZ_EC1)
#define OFF_DC0 (OFF_DG0+SZ_DG0)
#define OFF_DG1 (OFF_DC0+SZ_DC0)
#define OFF_DC1 (OFF_DG1+SZ_EG1)
#define WRE_TOTAL (OFF_DC1+SZ_EC1)

__device__ float g_WhhT[HH*3*HH];
__device__ float g_Wre[WRE_TOTAL];
__device__ float g_hgru[NB*HH];
__device__ float g_outs[TT*NB*HH];
__device__ float g_att[TT*NB];
__device__ float g_pooled[NB*HH];
__device__ float g_keym[NB*DHH];
__device__ float g_qm[NB*DHH];
__device__ float g_adj[BB*NN2];
__device__ float g_rowinv[NB];
__device__ float g_colinv[NB];
__device__ int   g_s1i[(size_t)NB*CAP1];
__device__ float g_s1v[(size_t)NB*CAP1];
__device__ int   g_s1c[NB];
__device__ int   g_s2i[(size_t)NB*CAP2];
__device__ float g_s2v[(size_t)NB*CAP2];
__device__ int   g_s2c[NB];
__device__ float g_xm[(size_t)MM*NB*256];
__device__ float g_ru[NB*HH2];
__device__ float g_h0[NB*HH];
__device__ float g_h1[NB*HH];
__device__ float g_go[NB];

__device__ __forceinline__ float sigf(float x){ return 1.f/(1.f+expf(-x)); }

__device__ __forceinline__ unsigned long long pk2(float x){
    unsigned long long r; asm("mov.b64 %0,{%1,%1};":"=l"(r):"f"(x)); return r;
}
__device__ __forceinline__ unsigned long long f2fma(unsigned long long a, unsigned long long b, unsigned long long c){
    unsigned long long d; asm("fma.rn.f32x2 %0,%1,%2,%3;":"=l"(d):"l"(a),"l"(b),"l"(c)); return d;
}
__device__ __forceinline__ float2 up2(unsigned long long v){
    float2 f; asm("mov.b64 {%0,%1},%2;":"=f"(f.x),"=f"(f.y):"l"(v)); return f;
}

__global__ void zero_k(float* p, int n){
    int i = blockIdx.x*blockDim.x+threadIdx.x;
    if (i < n) p[i] = 0.f;
}

__global__ void transpose_whh(const float* __restrict__ Whh){
    int idx = blockIdx.x*blockDim.x+threadIdx.x;
    if (idx >= 3*HH*HH) return;
    int j = idx/HH, k = idx%HH;
    g_WhhT[k*(3*HH)+j] = Whh[j*HH+k];
}

__global__ void reorder_w(const float* __restrict__ W, float* __restrict__ Wre, int D, int OUT){
    int idx = blockIdx.x*blockDim.x+threadIdx.x;
    if (idx >= D*MM*OUT) return;
    int o = idx%OUT; int t2 = idx/OUT; int d = t2%D; int m = t2/D;
    Wre[idx] = W[(d*MM+m)*OUT+o];
}

// ---------------- GRU: 8 rows per block ----------------
__global__ void __launch_bounds__(128) gru_step(
    const float* __restrict__ e, int t,
    const float* __restrict__ Wih, const float* __restrict__ bih,
    const float* __restrict__ bhh, float* __restrict__ h, float* __restrict__ outs)
{
    __shared__ float hs[8][HH];
    int tid = threadIdx.x;
    int r0 = blockIdx.x*8;
    #pragma unroll
    for (int q = 0; q < 8; q++) hs[q][tid] = h[(r0+q)*HH+tid];
    __syncthreads();
    float a0[8], a1[8], a2[8];
    #pragma unroll
    for (int q = 0; q < 8; q++){ a0[q]=0.f; a1[q]=0.f; a2[q]=0.f; }
    for (int k = 0; k < HH; k++){
        float w0 = g_WhhT[k*384+tid];
        float w1 = g_WhhT[k*384+HH+tid];
        float w2 = g_WhhT[k*384+2*HH+tid];
        #pragma unroll
        for (int q = 0; q < 8; q++){
            float hk = hs[q][k];
            a0[q] += hk*w0; a1[q] += hk*w1; a2[q] += hk*w2;
        }
    }
    float b0 = bhh[tid], b1 = bhh[HH+tid], b2 = bhh[2*HH+tid];
    float wi0a=Wih[tid*2], wi0b=Wih[tid*2+1];
    float wi1a=Wih[(HH+tid)*2], wi1b=Wih[(HH+tid)*2+1];
    float wi2a=Wih[(2*HH+tid)*2], wi2b=Wih[(2*HH+tid)*2+1];
    float bi0=bih[tid], bi1=bih[HH+tid], bi2=bih[2*HH+tid];
    #pragma unroll
    for (int q = 0; q < 8; q++){
        int r = r0+q;
        int n = r >> 5, b = r & 31;
        const float* x = e + (((size_t)b*TT+t)*NN_+n)*DIN_;
        float x0 = x[0], x1 = x[1];
        float ir = x0*wi0a + x1*wi0b + bi0;
        float iz = x0*wi1a + x1*wi1b + bi1;
        float ig = x0*wi2a + x1*wi2b + bi2;
        float rg = sigf(ir + a0[q] + b0);
        float zg = sigf(iz + a1[q] + b1);
        float ng = tanhf(ig + rg*(a2[q] + b2));
        float hn = (1.f-zg)*ng + zg*hs[q][tid];
        h[r*HH+tid] = hn;
        outs[(((size_t)t*NN_+n)*BB+b)*HH+tid] = hn;
    }
}

__global__ void att_score(const float* __restrict__ outs, const float* __restrict__ attW,
                          const float* __restrict__ attb, const float* __restrict__ wlc,
                          float* __restrict__ z)
{
    int warp = threadIdx.x >> 5, lane = threadIdx.x & 31;
    int row = blockIdx.x*8 + warp;
    if (row >= TT*NB) return;
    const float* o = outs + (size_t)row*HH;
    float o0=o[lane], o1=o[32+lane], o2=o[64+lane], o3=o[96+lane];
    float acc = 0.f;
    for (int d = 0; d < DHH; d++){
        const float* w = attW + d*HH;
        float p = w[lane]*o0 + w[32+lane]*o1 + w[64+lane]*o2 + w[96+lane]*o3;
        p += __shfl_xor_sync(0xffffffffu,p,16);
        p += __shfl_xor_sync(0xffffffffu,p,8);
        p += __shfl_xor_sync(0xffffffffu,p,4);
        p += __shfl_xor_sync(0xffffffffu,p,2);
        p += __shfl_xor_sync(0xffffffffu,p,1);
        acc += wlc[d]*fmaxf(p + attb[d], 0.f);
    }
    if (lane == 0) z[row] = acc;
}

__global__ void att_softmax_t(float* __restrict__ z){
    int idx = blockIdx.x*blockDim.x+threadIdx.x;
    if (idx >= NB) return;
    float v[TT]; float m = -3.0e38f;
    #pragma unroll
    for (int t = 0; t < TT; t++){ v[t] = z[t*NB+idx]; m = fmaxf(m, v[t]); }
    float s = 0.f;
    #pragma unroll
    for (int t = 0; t < TT; t++){ v[t] = expf(v[t]-m); s += v[t]; }
    float inv = 1.f/s;
    #pragma unroll
    for (int t = 0; t < TT; t++) z[t*NB+idx] = v[t]*inv;
}

__global__ void pooled_k(const float* __restrict__ outs, const float* __restrict__ att,
                         float* __restrict__ pooled)
{
    int idx = blockIdx.x*blockDim.x+threadIdx.x;
    if (idx >= NB*HH) return;
    int hh = idx & 127;
    int r = idx >> 7;
    int b = r/NN_, n = r%NN_;
    float acc = 0.f;
    #pragma unroll
    for (int t = 0; t < TT; t++)
        acc += outs[(((size_t)t*NN_+n)*BB+b)*HH+hh] * att[t*NB + n*BB + b];
    pooled[idx] = acc;
}

__global__ void keyqm_k(const float* __restrict__ pooled, const float* __restrict__ wkey,
                        const float* __restrict__ wq, float* __restrict__ keym,
                        float* __restrict__ qm)
{
    int idx = blockIdx.x*blockDim.x+threadIdx.x;
    if (idx >= NB*DHH) return;
    int d = idx % DHH;
    int r = idx / DHH;
    float ak = 0.f, aq = 0.f;
    for (int hh = 0; hh < HH; hh++){
        float p = pooled[r*HH+hh];
        ak += p*wkey[hh*DHH+d];
        aq += p*wq[hh*DHH+d];
    }
    keym[idx] = ak; qm[idx] = aq;
}

__global__ void __launch_bounds__(256) attn_row(
    const float* __restrict__ keym, const float* __restrict__ qm,
    const int* __restrict__ topk, float* __restrict__ adj, float* __restrict__ rowinv)
{
    __shared__ float krow[DHH];
    __shared__ float red[256];
    __shared__ float srt[256];
    const float inv_sqrt_h = 0.08838834764831845f;
    int b = blockIdx.x/NN_, i = blockIdx.x%NN_;
    int tid = threadIdx.x;
    if (tid < DHH) krow[tid] = keym[(b*NN_+i)*DHH+tid];
    __syncthreads();
    float a = -3.0e38f;
    if (tid < NN_){
        const float* q = qm + (b*NN_+tid)*DHH;
        float acc = 0.f;
        #pragma unroll 8
        for (int d = 0; d < DHH; d++) acc += krow[d]*q[d];
        a = acc*inv_sqrt_h;
    }
    red[tid] = a; __syncthreads();
    for (int s = 128; s > 0; s >>= 1){
        if (tid < s) red[tid] = fmaxf(red[tid], red[tid+s]);
        __syncthreads();
    }
    float mx = red[0]; __syncthreads();
    float e = (tid < NN_) ? expf(a-mx) : 0.f;
    red[tid] = e; __syncthreads();
    for (int s = 128; s > 0; s >>= 1){
        if (tid < s) red[tid] += red[tid+s];
        __syncthreads();
    }
    float sum = red[0]; __syncthreads();
    float at = (tid < NN_) ? e/sum : 0.f;
    srt[tid] = (tid < NN_) ? at : -3.0e38f;
    for (int k2 = 2; k2 <= 256; k2 <<= 1){
        for (int j = k2>>1; j > 0; j >>= 1){
            __syncthreads();
            int ixj = tid ^ j;
            if (ixj > tid){
                float x = srt[tid], y = srt[ixj];
                bool asc = ((tid & k2) == 0);
                if ((x > y) == asc){ srt[tid] = y; srt[ixj] = x; }
            }
        }
    }
    __syncthreads();
    int tk = topk ? *topk : 20;
    float kth = srt[256-tk];
    float ad = (tid < NN_ && at >= kth) ? at : 0.f;
    if (tid == i) ad += 1.f;
    if (tid < NN_) adj[(size_t)b*NN2 + i*NN_ + tid] = ad;
    __syncthreads();
    red[tid] = (tid < NN_) ? ad : 0.f;
    __syncthreads();
    for (int s = 128; s > 0; s >>= 1){
        if (tid < s) red[tid] += red[tid+s];
        __syncthreads();
    }
    if (tid == 0){
        float rs = red[0];
        rowinv[b*NN_+i] = (rs == 0.f) ? 0.f : 1.f/rs;
    }
}

__global__ void colsum_k(const float* __restrict__ adj, float* __restrict__ colinv){
    int idx = blockIdx.x*blockDim.x+threadIdx.x;
    if (idx >= NB) return;
    int b = idx/NN_, j = idx%NN_;
    float s = 0.f;
    for (int i = 0; i < NN_; i++) s += adj[(size_t)b*NN2 + i*NN_ + j];
    colinv[idx] = (s == 0.f) ? 0.f : 1.f/s;
}

__global__ void csr_build(const float* __restrict__ adj, const float* __restrict__ rowinv,
                          const float* __restrict__ colinv,
                          int* __restrict__ s1i, float* __restrict__ s1v, int* __restrict__ s1c,
                          int* __restrict__ s2i, float* __restrict__ s2v, int* __restrict__ s2c)
{
    int r = blockIdx.x*blockDim.x+threadIdx.x;
    if (r >= NB) return;
    int b = r/NN_, i = r%NN_;
    const float* A = adj + (size_t)b*NN2;
    int c2 = 0;
    for (int j = 0; j < NN_; j++){
        float a = A[i*NN_+j];
        if (a != 0.f && c2 < CAP2){
            s2i[(size_t)r*CAP2+c2] = j;
            s2v[(size_t)r*CAP2+c2] = a*colinv[b*NN_+j];
            c2++;
        }
    }
    s2c[r] = c2;
    int c1 = 0;
    for (int j = 0; j < NN_; j++){
        float a = A[j*NN_+i];
        if (a != 0.f){
            s1i[(size_t)r*CAP1+c1] = j;
            s1v[(size_t)r*CAP1+c1] = a*rowinv[b*NN_+j];
            c1++;
        }
    }
    s1c[r] = c1;
}

// concat [x, (r*)h] into plane0, columns [dstart, Dc)
__global__ void cat_k(const float* __restrict__ xb, int xbstr, int xnstr, int Dx,
                      const float* __restrict__ h, const float* __restrict__ ru,
                      float* __restrict__ plane0, int Dc, int dstart)
{
    int w = Dc - dstart;
    int idx = blockIdx.x*blockDim.x+threadIdx.x;
    if (idx >= NB*w) return;
    int d = dstart + idx % w;
    int r = idx / w;
    int b = r/NN_, n = r%NN_;
    float v;
    if (d < Dx){
        v = xb[(size_t)b*xbstr + n*xnstr + d];
    } else {
        int dh = d - Dx;
        v = h[r*HH + dh];
        if (ru) v *= ru[r*HH2 + dh];
    }
    plane0[(size_t)r*Dc + d] = v;
}

// Fused Chebyshev spmm: block = (col-tile, batch, support).
// Loads X0 tile (200 x 32) into smem, computes Y1 = S@X0 (kept in regs + written
// to smem + gmem), then Y2 = 2*S@Y1 - X0, both steps in one launch. L2 gather
// traffic drops ~21x vs per-row gather spmm.
__global__ void __launch_bounds__(256) cheb_k(
    float* __restrict__ xm, int D, int dstart)
{
    __shared__ float Xs[NN_][CT+1];
    int ct = blockIdx.x, b = blockIdx.y, z = blockIdx.z;
    size_t PL = (size_t)NB*D;
    const float* X0g = xm;
    float* Y1g = xm + (z==0 ? 1 : 3)*PL;
    float* Y2g = xm + (z==0 ? 2 : 4)*PL;
    int d0 = dstart + ct*CT;
    int tid = threadIdx.x;
    int dl = tid & 31, wid = tid >> 5;   // 8 warps, 25 rows each
    int d = d0 + dl;
    bool dok = (d < D);

    for (int idx = tid; idx < NN_*CT; idx += 256){
        int col = idx & (CT-1), row = idx >> 5;
        int dd = d0 + col;
        Xs[row][col] = (dd < D) ? X0g[(size_t)(b*NN_+row)*D + dd] : 0.f;
    }
    __syncthreads();

    const int* Ibase; const float* Vbase; const int* Cbase; int cap;
    if (z == 0){ Ibase = g_s1i; Vbase = g_s1v; Cbase = g_s1c; cap = CAP1; }
    else       { Ibase = g_s2i; Vbase = g_s2v; Cbase = g_s2c; cap = CAP2; }

    float y1[25];
    #pragma unroll
    for (int q = 0; q < 25; q++){
        int i = wid + q*8;
        int r = b*NN_ + i;
        const int* Ip = Ibase + (size_t)r*cap;
        const float* Vp = Vbase + (size_t)r*cap;
        int cnt = Cbase[r];
        float acc = 0.f;
        for (int k = 0; k < cnt; k++)
            acc += Vp[k]*Xs[Ip[k]][dl];
        y1[q] = acc;
    }
    __syncthreads();
    #pragma unroll
    for (int q = 0; q < 25; q++){
        int i = wid + q*8;
        Xs[i][dl] = y1[q];
        if (dok) Y1g[(size_t)(b*NN_+i)*D + d] = y1[q];
    }
    __syncthreads();
    #pragma unroll
    for (int q = 0; q < 25; q++){
        int i = wid + q*8;
        int r = b*NN_ + i;
        const int* Ip = Ibase + (size_t)r*cap;
        const float* Vp = Vbase + (size_t)r*cap;
        int cnt = Cbase[r];
        float acc = 0.f;
        for (int k = 0; k < cnt; k++)
            acc += Vp[k]*Xs[Ip[k]][dl];
        if (dok) Y2g[(size_t)r*D + d] = 2.f*acc - X0g[(size_t)r*D + d];
    }
}

// 64x64-tile GEMM over 5 planes, f32x2 packed FMA; fused epilogue.
__global__ void __launch_bounds__(256) dense_mm(
    const float* __restrict__ Xm, int D,
    const float* __restrict__ Wre, const float* __restrict__ bias,
    int OUT, float* __restrict__ C,
    const float* __restrict__ ruh, float* __restrict__ hbuf)
{
    __shared__ float As[16][64];
    __shared__ float Bs[16][64];
    int tid = threadIdx.x;
    int row0 = blockIdx.x*64, col0 = blockIdx.y*64;
    int tx = tid & 15, ty = tid >> 4;
    unsigned long long acc[4][2];
    #pragma unroll
    for (int i = 0; i < 4; i++){ acc[i][0] = 0ull; acc[i][1] = 0ull; }
    size_t PL = (size_t)NB*D;
    for (int m = 0; m < MM; m++){
        const float* Xp = Xm + m*PL;
        const float* Wp = Wre + (size_t)m*D*OUT;
        for (int k0 = 0; k0 < D; k0 += 16){
            #pragma unroll
            for (int e = 0; e < 4; e++){
                int idx = tid*4+e;
                int r = idx >> 4, kk = idx & 15;
                As[kk][r] = (k0+kk < D) ? Xp[(size_t)(row0+r)*D + k0+kk] : 0.f;
            }
            #pragma unroll
            for (int e = 0; e < 4; e++){
                int idx = tid*4+e;
                int kk = idx >> 6, nn = idx & 63;
                Bs[kk][nn] = (k0+kk < D) ? Wp[(size_t)(k0+kk)*OUT + col0+nn] : 0.f;
            }
            __syncthreads();
            #pragma unroll
            for (int kk = 0; kk < 16; kk++){
                float4 av = *reinterpret_cast<const float4*>(&As[kk][ty*4]);
                const unsigned long long* bp = reinterpret_cast<const unsigned long long*>(&Bs[kk][tx*4]);
                unsigned long long b0 = bp[0], b1 = bp[1];
                unsigned long long a;
                a = pk2(av.x); acc[0][0] = f2fma(a,b0,acc[0][0]); acc[0][1] = f2fma(a,b1,acc[0][1]);
                a = pk2(av.y); acc[1][0] = f2fma(a,b0,acc[1][0]); acc[1][1] = f2fma(a,b1,acc[1][1]);
                a = pk2(av.z); acc[2][0] = f2fma(a,b0,acc[2][0]); acc[2][1] = f2fma(a,b1,acc[2][1]);
                a = pk2(av.w); acc[3][0] = f2fma(a,b0,acc[3][0]); acc[3][1] = f2fma(a,b1,acc[3][1]);
            }
            __syncthreads();
        }
    }
    #pragma unroll
    for (int i = 0; i < 4; i++){
        int rr = row0 + ty*4 + i;
        #pragma unroll
        for (int jp = 0; jp < 2; jp++){
            float2 f = up2(acc[i][jp]);
            #pragma unroll
            for (int u2 = 0; u2 < 2; u2++){
                int cc = col0 + tx*4 + jp*2 + u2;
                float v = (u2 == 0 ? f.x : f.y) + bias[cc];
                if (hbuf){
                    float c = tanhf(v);
                    float u = ruh[(size_t)rr*HH2 + HH + cc];
                    float hold = hbuf[(size_t)rr*HH + cc];
                    hbuf[(size_t)rr*HH + cc] = u*hold + (1.f-u)*c;
                } else {
                    C[(size_t)rr*OUT + cc] = 1.f/(1.f+expf(-v));
                }
            }
        }
    }
}

__global__ void proj_k(const float* __restrict__ h1, const float* __restrict__ pw,
                       const float* __restrict__ pb, float* __restrict__ outp,
                       float* __restrict__ go)
{
    int warp = threadIdx.x >> 5, lane = threadIdx.x & 31;
    int row = blockIdx.x*8 + warp;
    if (row >= NB) return;
    const float* hr = h1 + (size_t)row*HH;
    float a = hr[lane]*pw[lane] + hr[32+lane]*pw[32+lane]
            + hr[64+lane]*pw[64+lane] + hr[96+lane]*pw[96+lane];
    a += __shfl_xor_sync(0xffffffffu,a,16);
    a += __shfl_xor_sync(0xffffffffu,a,8);
    a += __shfl_xor_sync(0xffffffffu,a,4);
    a += __shfl_xor_sync(0xffffffffu,a,2);
    a += __shfl_xor_sync(0xffffffffu,a,1);
    if (lane == 0){
        float v = a + pb[0];
        outp[row] = v;
        go[row] = v;
    }
}

extern "C" void kernel_launch(void* const* d_in, const int* in_sizes, int n_in,
                              void* d_out, int out_size)
{
    const float* enc  = (const float*)d_in[0];
    const float* Wih  = (const float*)d_in[2];
    const float* Whh  = (const float*)d_in[3];
    const float* bih  = (const float*)d_in[4];
    const float* bhh  = (const float*)d_in[5];
    const float* attW = (const float*)d_in[6];
    const float* attb = (const float*)d_in[7];
    const float* wlc  = (const float*)d_in[8];
    const float* wkey = (const float*)d_in[9];
    const float* wq   = (const float*)d_in[10];
    const float* eg0  = (const float*)d_in[11];
    const float* ebg0 = (const float*)d_in[12];
    const float* ec0  = (const float*)d_in[13];
    const float* ebc0 = (const float*)d_in[14];
    const float* eg1  = (const float*)d_in[15];
    const float* ebg1 = (const float*)d_in[16];
    const float* ec1  = (const float*)d_in[17];
    const float* ebc1 = (const float*)d_in[18];
    const float* dg0  = (const float*)d_in[19];
    const float* dbg0 = (const float*)d_in[20];
    const float* dc0  = (const float*)d_in[21];
    const float* dbc0 = (const float*)d_in[22];
    const float* dg1  = (const float*)d_in[23];
    const float* dbg1 = (const float*)d_in[24];
    const float* dc1  = (const float*)d_in[25];
    const float* dbc1 = (const float*)d_in[26];
    const float* pw   = (const float*)d_in[27];
    const float* pb   = (const float*)d_in[28];
    const int*  topk  = (n_in > 29) ? (const int*)d_in[29] : nullptr;
    float* out = (float*)d_out;

    float *wre,*hgru,*outs,*att,*pooled,*keym,*qm,*adj,*rowinv,*colinv,*xm,*rub,*h0,*h1,*go;
    int *s1i,*s1c,*s2i,*s2c; float *s1v,*s2v;
    cudaGetSymbolAddress((void**)&wre, g_Wre);
    cudaGetSymbolAddress((void**)&hgru, g_hgru);
    cudaGetSymbolAddress((void**)&outs, g_outs);
    cudaGetSymbolAddress((void**)&att, g_att);
    cudaGetSymbolAddress((void**)&pooled, g_pooled);
    cudaGetSymbolAddress((void**)&keym, g_keym);
    cudaGetSymbolAddress((void**)&qm, g_qm);
    cudaGetSymbolAddress((void**)&adj, g_adj);
    cudaGetSymbolAddress((void**)&rowinv, g_rowinv);
    cudaGetSymbolAddress((void**)&colinv, g_colinv);
    cudaGetSymbolAddress((void**)&s1i, g_s1i);
    cudaGetSymbolAddress((void**)&s1v, g_s1v);
    cudaGetSymbolAddress((void**)&s1c, g_s1c);
    cudaGetSymbolAddress((void**)&s2i, g_s2i);
    cudaGetSymbolAddress((void**)&s2v, g_s2v);
    cudaGetSymbolAddress((void**)&s2c, g_s2c);
    cudaGetSymbolAddress((void**)&xm, g_xm);
    cudaGetSymbolAddress((void**)&rub, g_ru);
    cudaGetSymbolAddress((void**)&h0, g_h0);
    cudaGetSymbolAddress((void**)&h1, g_h1);
    cudaGetSymbolAddress((void**)&go, g_go);

    transpose_whh<<<(3*HH*HH+255)/256, 256>>>(Whh);
    reorder_w<<<(SZ_EG0+255)/256, 256>>>(eg0, wre+OFF_EG0, D0E, HH2);
    reorder_w<<<(SZ_EC0+255)/256, 256>>>(ec0, wre+OFF_EC0, D0E, HH);
    reorder_w<<<(SZ_EG1+255)/256, 256>>>(eg1, wre+OFF_EG1, D1_, HH2);
    reorder_w<<<(SZ_EC1+255)/256, 256>>>(ec1, wre+OFF_EC1, D1_, HH);
    reorder_w<<<(SZ_DG0+255)/256, 256>>>(dg0, wre+OFF_DG0, D0D, HH2);
    reorder_w<<<(SZ_DC0+255)/256, 256>>>(dc0, wre+OFF_DC0, D0D, HH);
    reorder_w<<<(SZ_EG1+255)/256, 256>>>(dg1, wre+OFF_DG1, D1_, HH2);
    reorder_w<<<(SZ_EC1+255)/256, 256>>>(dc1, wre+OFF_DC1, D1_, HH);

    zero_k<<<(NB*HH+255)/256, 256>>>(hgru, NB*HH);
    for (int t = 0; t < TT; t++)
        gru_step<<<NB/8, 128>>>(enc, t, Wih, bih, bhh, hgru, outs);

    att_score<<<(TT*NB)/8, 256>>>(outs, attW, attb, wlc, att);
    att_softmax_t<<<(NB+255)/256, 256>>>(att);
    pooled_k<<<(NB*HH+255)/256, 256>>>(outs, att, pooled);
    keyqm_k<<<(NB*DHH+255)/256, 256>>>(pooled, wkey, wq, keym, qm);
    attn_row<<<BB*NN_, 256>>>(keym, qm, topk, adj, rowinv);
    colsum_k<<<(NB+255)/256, 256>>>(adj, colinv);
    csr_build<<<(NB+255)/256, 256>>>(adj, rowinv, colinv, s1i, s1v, s1c, s2i, s2v, s2c);

    auto gconv = [&](const float* xb, int xbstr, int xnstr, int Dx, float* h,
                     const float* rmul, const float* Wp, const float* bias,
                     int OUT, float* Cout, float* hfuse){
        int Dc = Dx + HH;
        int dstart = rmul ? Dx : 0;     // candidate reuses gate's x-column planes
        int w = Dc - dstart;
        cat_k<<<(NB*w+255)/256, 256>>>(xb, xbstr, xnstr, Dx, h, rmul, xm, Dc, dstart);
        dim3 cg((w+CT-1)/CT, BB, 2);
        cheb_k<<<cg, 256>>>(xm, Dc, dstart);
        dense_mm<<<dim3(NB/64, OUT/64), 256>>>(xm, Dc, Wp, bias, OUT, Cout, rmul, hfuse);
    };
    auto cell = [&](const float* xb, int xbstr, int xnstr, int Dx, float* h,
                    const float* Wg, const float* bg, const float* Wc, const float* bc){
        gconv(xb, xbstr, xnstr, Dx, h, nullptr, Wg, bg, HH2, rub, nullptr);
        gconv(xb, xbstr, xnstr, Dx, h, rub,     Wc, bc, HH,  nullptr, h);
    };

    zero_k<<<(NB*HH+255)/256, 256>>>(h0, NB*HH);
    zero_k<<<(NB*HH+255)/256, 256>>>(h1, NB*HH);
    for (int t = 0; t < TT; t++){
        cell(enc + (size_t)t*NN_*DIN_, TT*NN_*DIN_, DIN_, DIN_, h0,
             wre+OFF_EG0, ebg0, wre+OFF_EC0, ebc0);
        cell(h0, NN_*HH, HH, HH, h1,
             wre+OFF_EG1, ebg1, wre+OFF_EC1, ebc1);
    }

    zero_k<<<(NB+255)/256, 256>>>(go, NB);
    for (int t = 0; t < TT; t++){
        cell(go, NN_, 1, 1, h0,
             wre+OFF_DG0, dbg0, wre+OFF_DC0, dbc0);
        cell(h0, NN_*HH, HH, HH, h1,
             wre+OFF_DG1, dbg1, wre+OFF_DC1, dbc1);
        proj_k<<<NB/8, 256>>>(h1, pw, pb, out + (size_t)t*NB, go);
    }
    (void)in_sizes; (void)out_size;
}

// round 13
// speedup vs baseline: 1.0423x; 1.0421x over previous
#include <cuda_runtime.h>
#include <math.h>

#define BB   32
#define TT   12
#define NN_  200
#define HH   128
#define DHH  64
#define DIN_ 2
#define MM   5
#define NB   6400
#define HH2  256
#define D0E  130
#define D0D  129
#define D1_  256
#define NN2  40000
#define CAP1 200
#define CAP2 32

#define SZ_EG0 (D0E*MM*HH2)
#define SZ_EC0 (D0E*MM*HH)
#define SZ_EG1 (D1_*MM*HH2)
#define SZ_EC1 (D1_*MM*HH)
#define SZ_DG0 (D0D*MM*HH2)
#define SZ_DC0 (D0D*MM*HH)
#define OFF_EG0 0
#define OFF_EC0 (OFF_EG0+SZ_EG0)
#define OFF_EG1 (OFF_EC0+SZ_EC0)
#define OFF_EC1 (OFF_EG1+SZ_EG1)
#define OFF_DG0 (OFF_EC1+SZ_EC1)
#define OFF_DC0 (OFF_DG0+SZ_DG0)
#define OFF_DG1 (OFF_DC0+SZ_DC0)
#define OFF_DC1 (OFF_DG1+SZ_EG1)
#define WRE_TOTAL (OFF_DC1+SZ_EC1)

__device__ float g_WhhT[HH*3*HH];
__device__ float g_Wre[WRE_TOTAL];
__device__ float g_hgru[NB*HH];
__device__ float g_outs[TT*NB*HH];
__device__ float g_att[TT*NB];
__device__ float g_pooled[NB*HH];
__device__ float g_keym[NB*DHH];
__device__ float g_qm[NB*DHH];
__device__ float g_adj[BB*NN2];
__device__ float g_rowinv[NB];
__device__ float g_colinv[NB];
__device__ int   g_s1i[(size_t)NB*CAP1];
__device__ float g_s1v[(size_t)NB*CAP1];
__device__ int   g_s1c[NB];
__device__ int   g_s2i[(size_t)NB*CAP2];
__device__ float g_s2v[(size_t)NB*CAP2];
__device__ int   g_s2c[NB];
__device__ float g_xm[(size_t)MM*NB*256];
__device__ float g_ru[NB*HH2];
__device__ float g_rh[NB*HH];
__device__ float g_h0[NB*HH];
__device__ float g_h1[NB*HH];
__device__ float g_go[NB];

__device__ __forceinline__ float sigf(float x){ return 1.f/(1.f+expf(-x)); }

__device__ __forceinline__ unsigned long long pk2(float x){
    unsigned long long r; asm("mov.b64 %0,{%1,%1};":"=l"(r):"f"(x)); return r;
}
__device__ __forceinline__ unsigned long long f2fma(unsigned long long a, unsigned long long b, unsigned long long c){
    unsigned long long d; asm("fma.rn.f32x2 %0,%1,%2,%3;":"=l"(d):"l"(a),"l"(b),"l"(c)); return d;
}
__device__ __forceinline__ float2 up2(unsigned long long v){
    float2 f; asm("mov.b64 {%0,%1},%2;":"=f"(f.x),"=f"(f.y):"l"(v)); return f;
}

__global__ void zero_k(float* p, int n){
    int i = blockIdx.x*blockDim.x+threadIdx.x;
    if (i < n) p[i] = 0.f;
}

__global__ void transpose_whh(const float* __restrict__ Whh){
    int idx = blockIdx.x*blockDim.x+threadIdx.x;
    if (idx >= 3*HH*HH) return;
    int j = idx/HH, k = idx%HH;
    g_WhhT[k*(3*HH)+j] = Whh[j*HH+k];
}

__global__ void reorder_w(const float* __restrict__ W, float* __restrict__ Wre, int D, int OUT){
    int idx = blockIdx.x*blockDim.x+threadIdx.x;
    if (idx >= D*MM*OUT) return;
    int o = idx%OUT; int t2 = idx/OUT; int d = t2%D; int m = t2/D;
    Wre[idx] = W[(d*MM+m)*OUT+o];
}

// ---------------- GRU: 8 rows per block ----------------
__global__ void __launch_bounds__(128) gru_step(
    const float* __restrict__ e, int t,
    const float* __restrict__ Wih, const float* __restrict__ bih,
    const float* __restrict__ bhh, float* __restrict__ h, float* __restrict__ outs)
{
    __shared__ float hs[8][HH];
    int tid = threadIdx.x;
    int r0 = blockIdx.x*8;
    #pragma unroll
    for (int q = 0; q < 8; q++) hs[q][tid] = h[(r0+q)*HH+tid];
    __syncthreads();
    float a0[8], a1[8], a2[8];
    #pragma unroll
    for (int q = 0; q < 8; q++){ a0[q]=0.f; a1[q]=0.f; a2[q]=0.f; }
    for (int k = 0; k < HH; k++){
        float w0 = g_WhhT[k*384+tid];
        float w1 = g_WhhT[k*384+HH+tid];
        float w2 = g_WhhT[k*384+2*HH+tid];
        #pragma unroll
        for (int q = 0; q < 8; q++){
            float hk = hs[q][k];
            a0[q] += hk*w0; a1[q] += hk*w1; a2[q] += hk*w2;
        }
    }
    float b0 = bhh[tid], b1 = bhh[HH+tid], b2 = bhh[2*HH+tid];
    float wi0a=Wih[tid*2], wi0b=Wih[tid*2+1];
    float wi1a=Wih[(HH+tid)*2], wi1b=Wih[(HH+tid)*2+1];
    float wi2a=Wih[(2*HH+tid)*2], wi2b=Wih[(2*HH+tid)*2+1];
    float bi0=bih[tid], bi1=bih[HH+tid], bi2=bih[2*HH+tid];
    #pragma unroll
    for (int q = 0; q < 8; q++){
        int r = r0+q;
        int n = r >> 5, b = r & 31;
        const float* x = e + (((size_t)b*TT+t)*NN_+n)*DIN_;
        float x0 = x[0], x1 = x[1];
        float ir = x0*wi0a + x1*wi0b + bi0;
        float iz = x0*wi1a + x1*wi1b + bi1;
        float ig = x0*wi2a + x1*wi2b + bi2;
        float rg = sigf(ir + a0[q] + b0);
        float zg = sigf(iz + a1[q] + b1);
        float ng = tanhf(ig + rg*(a2[q] + b2));
        float hn = (1.f-zg)*ng + zg*hs[q][tid];
        h[r*HH+tid] = hn;
        outs[(((size_t)t*NN_+n)*BB+b)*HH+tid] = hn;
    }
}

__global__ void att_score(const float* __restrict__ outs, const float* __restrict__ attW,
                          const float* __restrict__ attb, const float* __restrict__ wlc,
                          float* __restrict__ z)
{
    int warp = threadIdx.x >> 5, lane = threadIdx.x & 31;
    int row = blockIdx.x*8 + warp;
    if (row >= TT*NB) return;
    const float* o = outs + (size_t)row*HH;
    float o0=o[lane], o1=o[32+lane], o2=o[64+lane], o3=o[96+lane];
    float acc = 0.f;
    for (int d = 0; d < DHH; d++){
        const float* w = attW + d*HH;
        float p = w[lane]*o0 + w[32+lane]*o1 + w[64+lane]*o2 + w[96+lane]*o3;
        p += __shfl_xor_sync(0xffffffffu,p,16);
        p += __shfl_xor_sync(0xffffffffu,p,8);
        p += __shfl_xor_sync(0xffffffffu,p,4);
        p += __shfl_xor_sync(0xffffffffu,p,2);
        p += __shfl_xor_sync(0xffffffffu,p,1);
        acc += wlc[d]*fmaxf(p + attb[d], 0.f);
    }
    if (lane == 0) z[row] = acc;
}

__global__ void att_softmax_t(float* __restrict__ z){
    int idx = blockIdx.x*blockDim.x+threadIdx.x;
    if (idx >= NB) return;
    float v[TT]; float m = -3.0e38f;
    #pragma unroll
    for (int t = 0; t < TT; t++){ v[t] = z[t*NB+idx]; m = fmaxf(m, v[t]); }
    float s = 0.f;
    #pragma unroll
    for (int t = 0; t < TT; t++){ v[t] = expf(v[t]-m); s += v[t]; }
    float inv = 1.f/s;
    #pragma unroll
    for (int t = 0; t < TT; t++) z[t*NB+idx] = v[t]*inv;
}

__global__ void pooled_k(const float* __restrict__ outs, const float* __restrict__ att,
                         float* __restrict__ pooled)
{
    int idx = blockIdx.x*blockDim.x+threadIdx.x;
    if (idx >= NB*HH) return;
    int hh = idx & 127;
    int r = idx >> 7;
    int b = r/NN_, n = r%NN_;
    float acc = 0.f;
    #pragma unroll
    for (int t = 0; t < TT; t++)
        acc += outs[(((size_t)t*NN_+n)*BB+b)*HH+hh] * att[t*NB + n*BB + b];
    pooled[idx] = acc;
}

__global__ void keyqm_k(const float* __restrict__ pooled, const float* __restrict__ wkey,
                        const float* __restrict__ wq, float* __restrict__ keym,
                        float* __restrict__ qm)
{
    int idx = blockIdx.x*blockDim.x+threadIdx.x;
    if (idx >= NB*DHH) return;
    int d = idx % DHH;
    int r = idx / DHH;
    float ak = 0.f, aq = 0.f;
    for (int hh = 0; hh < HH; hh++){
        float p = pooled[r*HH+hh];
        ak += p*wkey[hh*DHH+d];
        aq += p*wq[hh*DHH+d];
    }
    keym[idx] = ak; qm[idx] = aq;
}

__global__ void __launch_bounds__(256) attn_row(
    const float* __restrict__ keym, const float* __restrict__ qm,
    const int* __restrict__ topk, float* __restrict__ adj, float* __restrict__ rowinv)
{
    __shared__ float krow[DHH];
    __shared__ float red[256];
    __shared__ float srt[256];
    const float inv_sqrt_h = 0.08838834764831845f;
    int b = blockIdx.x/NN_, i = blockIdx.x%NN_;
    int tid = threadIdx.x;
    if (tid < DHH) krow[tid] = keym[(b*NN_+i)*DHH+tid];
    __syncthreads();
    float a = -3.0e38f;
    if (tid < NN_){
        const float* q = qm + (b*NN_+tid)*DHH;
        float acc = 0.f;
        #pragma unroll 8
        for (int d = 0; d < DHH; d++) acc += krow[d]*q[d];
        a = acc*inv_sqrt_h;
    }
    red[tid] = a; __syncthreads();
    for (int s = 128; s > 0; s >>= 1){
        if (tid < s) red[tid] = fmaxf(red[tid], red[tid+s]);
        __syncthreads();
    }
    float mx = red[0]; __syncthreads();
    float e = (tid < NN_) ? expf(a-mx) : 0.f;
    red[tid] = e; __syncthreads();
    for (int s = 128; s > 0; s >>= 1){
        if (tid < s) red[tid] += red[tid+s];
        __syncthreads();
    }
    float sum = red[0]; __syncthreads();
    float at = (tid < NN_) ? e/sum : 0.f;
    srt[tid] = (tid < NN_) ? at : -3.0e38f;
    for (int k2 = 2; k2 <= 256; k2 <<= 1){
        for (int j = k2>>1; j > 0; j >>= 1){
            __syncthreads();
            int ixj = tid ^ j;
            if (ixj > tid){
                float x = srt[tid], y = srt[ixj];
                bool asc = ((tid & k2) == 0);
                if ((x > y) == asc){ srt[tid] = y; srt[ixj] = x; }
            }
        }
    }
    __syncthreads();
    int tk = topk ? *topk : 20;
    float kth = srt[256-tk];
    float ad = (tid < NN_ && at >= kth) ? at : 0.f;
    if (tid == i) ad += 1.f;
    if (tid < NN_) adj[(size_t)b*NN2 + i*NN_ + tid] = ad;
    __syncthreads();
    red[tid] = (tid < NN_) ? ad : 0.f;
    __syncthreads();
    for (int s = 128; s > 0; s >>= 1){
        if (tid < s) red[tid] += red[tid+s];
        __syncthreads();
    }
    if (tid == 0){
        float rs = red[0];
        rowinv[b*NN_+i] = (rs == 0.f) ? 0.f : 1.f/rs;
    }
}

__global__ void colsum_k(const float* __restrict__ adj, float* __restrict__ colinv){
    int idx = blockIdx.x*blockDim.x+threadIdx.x;
    if (idx >= NB) return;
    int b = idx/NN_, j = idx%NN_;
    float s = 0.f;
    for (int i = 0; i < NN_; i++) s += adj[(size_t)b*NN2 + i*NN_ + j];
    colinv[idx] = (s == 0.f) ? 0.f : 1.f/s;
}

__global__ void csr_build(const float* __restrict__ adj, const float* __restrict__ rowinv,
                          const float* __restrict__ colinv,
                          int* __restrict__ s1i, float* __restrict__ s1v, int* __restrict__ s1c,
                          int* __restrict__ s2i, float* __restrict__ s2v, int* __restrict__ s2c)
{
    int r = blockIdx.x*blockDim.x+threadIdx.x;
    if (r >= NB) return;
    int b = r/NN_, i = r%NN_;
    const float* A = adj + (size_t)b*NN2;
    int c2 = 0;
    for (int j = 0; j < NN_; j++){
        float a = A[i*NN_+j];
        if (a != 0.f && c2 < CAP2){
            s2i[(size_t)r*CAP2+c2] = j;
            s2v[(size_t)r*CAP2+c2] = a*colinv[b*NN_+j];
            c2++;
        }
    }
    s2c[r] = c2;
    int c1 = 0;
    for (int j = 0; j < NN_; j++){
        float a = A[j*NN_+i];
        if (a != 0.f){
            s1i[(size_t)r*CAP1+c1] = j;
            s1v[(size_t)r*CAP1+c1] = a*rowinv[b*NN_+j];
            c1++;
        }
    }
    s1c[r] = c1;
}

// sparse spmm with inline concat source. step1: Y=S@src -> plane 1/3.
// step2: Y=2*S@plane(1/3) - src -> plane 2/4.
__global__ void spmm_sp(
    const float* __restrict__ xb, int xbstr, int xnstr, int Dx,
    const float* __restrict__ hs,   // h (gate) or rh (candidate)
    float* __restrict__ xm, int D, int dstart, int step)
{
    __shared__ int sj[CAP1];
    __shared__ float sv[CAP1];
    int i = blockIdx.x, b = blockIdx.y, z = blockIdx.z;
    int r = b*NN_ + i;
    const int* Ip; const float* Vp; int cnt;
    if (z == 0){ Ip = g_s1i + (size_t)r*CAP1; Vp = g_s1v + (size_t)r*CAP1; cnt = g_s1c[r]; }
    else       { Ip = g_s2i + (size_t)r*CAP2; Vp = g_s2v + (size_t)r*CAP2; cnt = g_s2c[r]; }
    for (int k = threadIdx.x; k < cnt; k += blockDim.x){ sj[k] = Ip[k]; sv[k] = Vp[k]; }
    __syncthreads();
    int d = dstart + threadIdx.x;
    if (d >= D) return;
    size_t PL = (size_t)NB*D;
    float acc = 0.f;
    if (step == 1){
        float* Y = xm + (size_t)(z==0 ? 1 : 3)*PL;
        if (d < Dx){
            const float* xbb = xb + (size_t)b*xbstr + d;
            int k = 0;
            for (; k+4 <= cnt; k += 4){
                float a0 = sv[k]  *xbb[(size_t)sj[k]*xnstr];
                float a1 = sv[k+1]*xbb[(size_t)sj[k+1]*xnstr];
                float a2 = sv[k+2]*xbb[(size_t)sj[k+2]*xnstr];
                float a3 = sv[k+3]*xbb[(size_t)sj[k+3]*xnstr];
                acc += (a0+a1)+(a2+a3);
            }
            for (; k < cnt; k++) acc += sv[k]*xbb[(size_t)sj[k]*xnstr];
        } else {
            const float* hb = hs + ((size_t)b*NN_)*HH + (d - Dx);
            int k = 0;
            for (; k+4 <= cnt; k += 4){
                float a0 = sv[k]  *hb[(size_t)sj[k]*HH];
                float a1 = sv[k+1]*hb[(size_t)sj[k+1]*HH];
                float a2 = sv[k+2]*hb[(size_t)sj[k+2]*HH];
                float a3 = sv[k+3]*hb[(size_t)sj[k+3]*HH];
                acc += (a0+a1)+(a2+a3);
            }
            for (; k < cnt; k++) acc += sv[k]*hb[(size_t)sj[k]*HH];
        }
        Y[(size_t)r*D + d] = acc;
    } else {
        const float* Xb = xm + (size_t)(z==0 ? 1 : 3)*PL + (size_t)b*NN_*D;
        float* Y = xm + (size_t)(z==0 ? 2 : 4)*PL;
        int k = 0;
        for (; k+4 <= cnt; k += 4){
            float a0 = sv[k]  *Xb[(size_t)sj[k]*D+d];
            float a1 = sv[k+1]*Xb[(size_t)sj[k+1]*D+d];
            float a2 = sv[k+2]*Xb[(size_t)sj[k+2]*D+d];
            float a3 = sv[k+3]*Xb[(size_t)sj[k+3]*D+d];
            acc += (a0+a1)+(a2+a3);
        }
        for (; k < cnt; k++) acc += sv[k]*Xb[(size_t)sj[k]*D+d];
        float xprev = (d < Dx) ? xb[(size_t)b*xbstr + (size_t)i*xnstr + d]
                               : hs[((size_t)b*NN_+i)*HH + (d - Dx)];
        Y[(size_t)r*D + d] = 2.f*acc - xprev;
    }
}

// 64x64-tile GEMM over 5 planes (plane 0 inline from concat source),
// f32x2 packed FMA, K-slice 32; fused epilogues:
//  gate (hbuf==0): C=sigmoid, rh = C[:,0:HH]*hs
//  cand (hbuf!=0): h = u*h + (1-u)*tanh(v)
__global__ void __launch_bounds__(256) dense_mm(
    const float* __restrict__ Xm, int D,
    const float* __restrict__ Wre, const float* __restrict__ bias,
    int OUT, float* __restrict__ C,
    const float* __restrict__ ruh, float* __restrict__ hbuf,
    const float* __restrict__ xb, int xbstr, int xnstr, int Dx,
    const float* __restrict__ hs, float* __restrict__ rh)
{
    __shared__ float As[32][64];
    __shared__ float Bs[32][64];
    int tid = threadIdx.x;
    int row0 = blockIdx.x*64, col0 = blockIdx.y*64;
    int tx = tid & 15, ty = tid >> 4;
    unsigned long long acc[4][2];
    #pragma unroll
    for (int i = 0; i < 4; i++){ acc[i][0] = 0ull; acc[i][1] = 0ull; }
    size_t PL = (size_t)NB*D;
    // staging maps
    int a_r  = (tid*8) >> 5;      // 0..63 (constant per thread)
    int a_k0 = (tid*8) & 31;      // 0,8,16,24
    int b_k  = (tid*8) >> 6;      // 0..31
    int b_c0 = (tid*8) & 63;      // 0,8,..,56
    int grow = row0 + a_r;
    int gb = grow / NN_, gn = grow % NN_;

    for (int m = 0; m < MM; m++){
        const float* Xp = Xm + (size_t)m*PL;
        const float* Wp = Wre + (size_t)m*D*OUT;
        for (int k0 = 0; k0 < D; k0 += 32){
            if (m == 0){
                #pragma unroll
                for (int u = 0; u < 8; u++){
                    int k = k0 + a_k0 + u;
                    float v = 0.f;
                    if (k < D){
                        if (k < Dx) v = xb[(size_t)gb*xbstr + (size_t)gn*xnstr + k];
                        else        v = hs[(size_t)grow*HH + (k - Dx)];
                    }
                    As[a_k0+u][a_r] = v;
                }
            } else {
                const float* xrow = Xp + (size_t)grow*D + k0 + a_k0;
                #pragma unroll
                for (int u = 0; u < 8; u++){
                    int k = k0 + a_k0 + u;
                    As[a_k0+u][a_r] = (k < D) ? xrow[u] : 0.f;
                }
            }
            {
                int k = k0 + b_k;
                const float* wrow = Wp + (size_t)k*OUT + col0 + b_c0;
                #pragma unroll
                for (int u = 0; u < 8; u++)
                    Bs[b_k][b_c0+u] = (k < D) ? wrow[u] : 0.f;
            }
            __syncthreads();
            #pragma unroll
            for (int kk = 0; kk < 32; kk++){
                float4 av = *reinterpret_cast<const float4*>(&As[kk][ty*4]);
                const unsigned long long* bp = reinterpret_cast<const unsigned long long*>(&Bs[kk][tx*4]);
                unsigned long long b0 = bp[0], b1 = bp[1];
                unsigned long long a;
                a = pk2(av.x); acc[0][0] = f2fma(a,b0,acc[0][0]); acc[0][1] = f2fma(a,b1,acc[0][1]);
                a = pk2(av.y); acc[1][0] = f2fma(a,b0,acc[1][0]); acc[1][1] = f2fma(a,b1,acc[1][1]);
                a = pk2(av.z); acc[2][0] = f2fma(a,b0,acc[2][0]); acc[2][1] = f2fma(a,b1,acc[2][1]);
                a = pk2(av.w); acc[3][0] = f2fma(a,b0,acc[3][0]); acc[3][1] = f2fma(a,b1,acc[3][1]);
            }
            __syncthreads();
        }
    }
    #pragma unroll
    for (int i = 0; i < 4; i++){
        int rr = row0 + ty*4 + i;
        #pragma unroll
        for (int jp = 0; jp < 2; jp++){
            float2 f = up2(acc[i][jp]);
            #pragma unroll
            for (int u2 = 0; u2 < 2; u2++){
                int cc = col0 + tx*4 + jp*2 + u2;
                float v = (u2 == 0 ? f.x : f.y) + bias[cc];
                if (hbuf){
                    float c = tanhf(v);
                    float u = ruh[(size_t)rr*HH2 + HH + cc];
                    float hold = hbuf[(size_t)rr*HH + cc];
                    hbuf[(size_t)rr*HH + cc] = u*hold + (1.f-u)*c;
                } else {
                    float s = 1.f/(1.f+expf(-v));
                    C[(size_t)rr*OUT + cc] = s;
                    if (rh && cc < HH)
                        rh[(size_t)rr*HH + cc] = s * hs[(size_t)rr*HH + cc];
                }
            }
        }
    }
}

__global__ void proj_k(const float* __restrict__ h1, const float* __restrict__ pw,
                       const float* __restrict__ pb, float* __restrict__ outp,
                       float* __restrict__ go)
{
    int warp = threadIdx.x >> 5, lane = threadIdx.x & 31;
    int row = blockIdx.x*8 + warp;
    if (row >= NB) return;
    const float* hr = h1 + (size_t)row*HH;
    float a = hr[lane]*pw[lane] + hr[32+lane]*pw[32+lane]
            + hr[64+lane]*pw[64+lane] + hr[96+lane]*pw[96+lane];
    a += __shfl_xor_sync(0xffffffffu,a,16);
    a += __shfl_xor_sync(0xffffffffu,a,8);
    a += __shfl_xor_sync(0xffffffffu,a,4);
    a += __shfl_xor_sync(0xffffffffu,a,2);
    a += __shfl_xor_sync(0xffffffffu,a,1);
    if (lane == 0){
        float v = a + pb[0];
        outp[row] = v;
        go[row] = v;
    }
}

extern "C" void kernel_launch(void* const* d_in, const int* in_sizes, int n_in,
                              void* d_out, int out_size)
{
    const float* enc  = (const float*)d_in[0];
    const float* Wih  = (const float*)d_in[2];
    const float* Whh  = (const float*)d_in[3];
    const float* bih  = (const float*)d_in[4];
    const float* bhh  = (const float*)d_in[5];
    const float* attW = (const float*)d_in[6];
    const float* attb = (const float*)d_in[7];
    const float* wlc  = (const float*)d_in[8];
    const float* wkey = (const float*)d_in[9];
    const float* wq   = (const float*)d_in[10];
    const float* eg0  = (const float*)d_in[11];
    const float* ebg0 = (const float*)d_in[12];
    const float* ec0  = (const float*)d_in[13];
    const float* ebc0 = (const float*)d_in[14];
    const float* eg1  = (const float*)d_in[15];
    const float* ebg1 = (const float*)d_in[16];
    const float* ec1  = (const float*)d_in[17];
    const float* ebc1 = (const float*)d_in[18];
    const float* dg0  = (const float*)d_in[19];
    const float* dbg0 = (const float*)d_in[20];
    const float* dc0  = (const float*)d_in[21];
    const float* dbc0 = (const float*)d_in[22];
    const float* dg1  = (const float*)d_in[23];
    const float* dbg1 = (const float*)d_in[24];
    const float* dc1  = (const float*)d_in[25];
    const float* dbc1 = (const float*)d_in[26];
    const float* pw   = (const float*)d_in[27];
    const float* pb   = (const float*)d_in[28];
    const int*  topk  = (n_in > 29) ? (const int*)d_in[29] : nullptr;
    float* out = (float*)d_out;

    float *wre,*hgru,*outs,*att,*pooled,*keym,*qm,*adj,*rowinv,*colinv,*xm,*rub,*rh,*h0,*h1,*go;
    int *s1i,*s1c,*s2i,*s2c; float *s1v,*s2v;
    cudaGetSymbolAddress((void**)&wre, g_Wre);
    cudaGetSymbolAddress((void**)&hgru, g_hgru);
    cudaGetSymbolAddress((void**)&outs, g_outs);
    cudaGetSymbolAddress((void**)&att, g_att);
    cudaGetSymbolAddress((void**)&pooled, g_pooled);
    cudaGetSymbolAddress((void**)&keym, g_keym);
    cudaGetSymbolAddress((void**)&qm, g_qm);
    cudaGetSymbolAddress((void**)&adj, g_adj);
    cudaGetSymbolAddress((void**)&rowinv, g_rowinv);
    cudaGetSymbolAddress((void**)&colinv, g_colinv);
    cudaGetSymbolAddress((void**)&s1i, g_s1i);
    cudaGetSymbolAddress((void**)&s1v, g_s1v);
    cudaGetSymbolAddress((void**)&s1c, g_s1c);
    cudaGetSymbolAddress((void**)&s2i, g_s2i);
    cudaGetSymbolAddress((void**)&s2v, g_s2v);
    cudaGetSymbolAddress((void**)&s2c, g_s2c);
    cudaGetSymbolAddress((void**)&xm, g_xm);
    cudaGetSymbolAddress((void**)&rub, g_ru);
    cudaGetSymbolAddress((void**)&rh, g_rh);
    cudaGetSymbolAddress((void**)&h0, g_h0);
    cudaGetSymbolAddress((void**)&h1, g_h1);
    cudaGetSymbolAddress((void**)&go, g_go);

    // setup: ordered so launch #6 (ncu -s 5) is a representative dense_mm
    transpose_whh<<<(3*HH*HH+255)/256, 256>>>(Whh);                       // 1
    reorder_w<<<(SZ_EG1+255)/256, 256>>>(eg1, wre+OFF_EG1, D1_, HH2);     // 2
    reorder_w<<<(SZ_EC1+255)/256, 256>>>(ec1, wre+OFF_EC1, D1_, HH);      // 3
    reorder_w<<<(SZ_EG1+255)/256, 256>>>(dg1, wre+OFF_DG1, D1_, HH2);     // 4
    reorder_w<<<(SZ_EC1+255)/256, 256>>>(dc1, wre+OFF_DC1, D1_, HH);      // 5
    // 6: profiling-representative dense GEMM (deterministic work; output g_ru
    // is overwritten by the first real gate GEMM before any consumer reads it)
    dense_mm<<<dim3(NB/64, HH2/64), 256>>>(xm, D1_, wre+OFF_EG1, ebg1, HH2,
                                           rub, nullptr, nullptr,
                                           nullptr, 0, 0, 0, outs, nullptr);
    reorder_w<<<(SZ_EG0+255)/256, 256>>>(eg0, wre+OFF_EG0, D0E, HH2);
    reorder_w<<<(SZ_EC0+255)/256, 256>>>(ec0, wre+OFF_EC0, D0E, HH);
    reorder_w<<<(SZ_DG0+255)/256, 256>>>(dg0, wre+OFF_DG0, D0D, HH2);
    reorder_w<<<(SZ_DC0+255)/256, 256>>>(dc0, wre+OFF_DC0, D0D, HH);

    zero_k<<<(NB*HH+255)/256, 256>>>(hgru, NB*HH);
    for (int t = 0; t < TT; t++)
        gru_step<<<NB/8, 128>>>(enc, t, Wih, bih, bhh, hgru, outs);

    att_score<<<(TT*NB)/8, 256>>>(outs, attW, attb, wlc, att);
    att_softmax_t<<<(NB+255)/256, 256>>>(att);
    pooled_k<<<(NB*HH+255)/256, 256>>>(outs, att, pooled);
    keyqm_k<<<(NB*DHH+255)/256, 256>>>(pooled, wkey, wq, keym, qm);
    attn_row<<<BB*NN_, 256>>>(keym, qm, topk, adj, rowinv);
    colsum_k<<<(NB+255)/256, 256>>>(adj, colinv);
    csr_build<<<(NB+255)/256, 256>>>(adj, rowinv, colinv, s1i, s1v, s1c, s2i, s2v, s2c);

    auto cell = [&](const float* xb, int xbstr, int xnstr, int Dx, float* h,
                    const float* Wg, const float* bg, const float* Wc, const float* bc){
        int Dc = Dx + HH;
        int nt = ((Dc+31)/32)*32; if (nt > 256) nt = 256;
        dim3 sg(NN_, BB, 2);
        // gate
        spmm_sp<<<sg, nt>>>(xb, xbstr, xnstr, Dx, h, xm, Dc, 0, 1);
        spmm_sp<<<sg, nt>>>(xb, xbstr, xnstr, Dx, h, xm, Dc, 0, 2);
        dense_mm<<<dim3(NB/64, HH2/64), 256>>>(xm, Dc, Wg, bg, HH2, rub, nullptr, nullptr,
                                               xb, xbstr, xnstr, Dx, h, rh);
        // candidate (x-columns of planes reused; h-columns recomputed from rh)
        spmm_sp<<<sg, 128>>>(xb, xbstr, xnstr, Dx, rh, xm, Dc, Dx, 1);
        spmm_sp<<<sg, 128>>>(xb, xbstr, xnstr, Dx, rh, xm, Dc, Dx, 2);
        dense_mm<<<dim3(NB/64, HH/64), 256>>>(xm, Dc, Wc, bc, HH, nullptr, rub, h,
                                              xb, xbstr, xnstr, Dx, rh, nullptr);
    };

    zero_k<<<(NB*HH+255)/256, 256>>>(h0, NB*HH);
    zero_k<<<(NB*HH+255)/256, 256>>>(h1, NB*HH);
    for (int t = 0; t < TT; t++){
        cell(enc + (size_t)t*NN_*DIN_, TT*NN_*DIN_, DIN_, DIN_, h0,
             wre+OFF_EG0, ebg0, wre+OFF_EC0, ebc0);
        cell(h0, NN_*HH, HH, HH, h1,
             wre+OFF_EG1, ebg1, wre+OFF_EC1, ebc1);
    }

    zero_k<<<(NB+255)/256, 256>>>(go, NB);
    for (int t = 0; t < TT; t++){
        cell(go, NN_, 1, 1, h0,
             wre+OFF_DG0, dbg0, wre+OFF_DC0, dbc0);
        cell(h0, NN_*HH, HH, HH, h1,
             wre+OFF_DG1, dbg1, wre+OFF_DC1, dbc1);
        proj_k<<<NB/8, 256>>>(h1, pw, pb, out + (size_t)t*NB, go);
    }
    (void)in_sizes; (void)out_size;
}

// round 14
// speedup vs baseline: 1.3895x; 1.3332x over previous
#include <cuda_runtime.h>
#include <math.h>

#define BB   32
#define TT   12
#define NN_  200
#define HH   128
#define DHH  64
#define DIN_ 2
#define MM   5
#define NB   6400
#define HH2  256
#define D0E  130
#define D0D  129
#define D1_  256
#define NN2  40000
#define CAP1 200
#define CAP2 32

#define SZ_EG0 (D0E*MM*HH2)
#define SZ_EC0 (D0E*MM*HH)
#define SZ_EG1 (D1_*MM*HH2)
#define SZ_EC1 (D1_*MM*HH)
#define SZ_DG0 (D0D*MM*HH2)
#define SZ_DC0 (D0D*MM*HH)
#define OFF_EG0 0
#define OFF_EC0 (OFF_EG0+SZ_EG0)
#define OFF_EG1 (OFF_EC0+SZ_EC0)
#define OFF_EC1 (OFF_EG1+SZ_EG1)
#define OFF_DG0 (OFF_EC1+SZ_EC1)
#define OFF_DC0 (OFF_DG0+SZ_DG0)
#define OFF_DG1 (OFF_DC0+SZ_DC0)
#define OFF_DC1 (OFF_DG1+SZ_EG1)
#define WRE_TOTAL (OFF_DC1+SZ_EC1)

__device__ float g_WhhT[HH*3*HH];
__device__ float g_Wre[WRE_TOTAL];
__device__ float g_hgru[NB*HH];
__device__ float g_outs[TT*NB*HH];
__device__ float g_att[TT*NB];
__device__ float g_pooled[NB*HH];
__device__ float g_keym[NB*DHH];
__device__ float g_qm[NB*DHH];
__device__ float g_adj[BB*NN2];
__device__ float g_rowinv[NB];
__device__ float g_colinv[NB];
__device__ int   g_s1i[(size_t)NB*CAP1];
__device__ float g_s1v[(size_t)NB*CAP1];
__device__ int   g_s1c[NB];
__device__ int   g_s2i[(size_t)NB*CAP2];
__device__ float g_s2v[(size_t)NB*CAP2];
__device__ int   g_s2c[NB];
__device__ float g_xm[(size_t)MM*NB*256];
__device__ float g_ru[NB*HH2];
__device__ float g_h0[NB*HH];
__device__ float g_h1[NB*HH];
__device__ float g_go[NB];

__device__ __forceinline__ float sigf(float x){ return 1.f/(1.f+expf(-x)); }

__device__ __forceinline__ unsigned long long pk2(float x){
    unsigned long long r; asm("mov.b64 %0,{%1,%1};":"=l"(r):"f"(x)); return r;
}
__device__ __forceinline__ unsigned long long f2fma(unsigned long long a, unsigned long long b, unsigned long long c){
    unsigned long long d; asm("fma.rn.f32x2 %0,%1,%2,%3;":"=l"(d):"l"(a),"l"(b),"l"(c)); return d;
}
__device__ __forceinline__ float2 up2(unsigned long long v){
    float2 f; asm("mov.b64 {%0,%1},%2;":"=f"(f.x),"=f"(f.y):"l"(v)); return f;
}

__global__ void zero_k(float* p, int n){
    int i = blockIdx.x*blockDim.x+threadIdx.x;
    if (i < n) p[i] = 0.f;
}

__global__ void transpose_whh(const float* __restrict__ Whh){
    int idx = blockIdx.x*blockDim.x+threadIdx.x;
    if (idx >= 3*HH*HH) return;
    int j = idx/HH, k = idx%HH;
    g_WhhT[k*(3*HH)+j] = Whh[j*HH+k];
}

__global__ void reorder_w(const float* __restrict__ W, float* __restrict__ Wre, int D, int OUT){
    int idx = blockIdx.x*blockDim.x+threadIdx.x;
    if (idx >= D*MM*OUT) return;
    int o = idx%OUT; int t2 = idx/OUT; int d = t2%D; int m = t2/D;
    Wre[idx] = W[(d*MM+m)*OUT+o];
}

// ---------------- GRU: 8 rows per block ----------------
__global__ void __launch_bounds__(128) gru_step(
    const float* __restrict__ e, int t,
    const float* __restrict__ Wih, const float* __restrict__ bih,
    const float* __restrict__ bhh, float* __restrict__ h, float* __restrict__ outs)
{
    __shared__ float hs[8][HH];
    int tid = threadIdx.x;
    int r0 = blockIdx.x*8;
    #pragma unroll
    for (int q = 0; q < 8; q++) hs[q][tid] = h[(r0+q)*HH+tid];
    __syncthreads();
    float a0[8], a1[8], a2[8];
    #pragma unroll
    for (int q = 0; q < 8; q++){ a0[q]=0.f; a1[q]=0.f; a2[q]=0.f; }
    for (int k = 0; k < HH; k++){
        float w0 = g_WhhT[k*384+tid];
        float w1 = g_WhhT[k*384+HH+tid];
        float w2 = g_WhhT[k*384+2*HH+tid];
        #pragma unroll
        for (int q = 0; q < 8; q++){
            float hk = hs[q][k];
            a0[q] += hk*w0; a1[q] += hk*w1; a2[q] += hk*w2;
        }
    }
    float b0 = bhh[tid], b1 = bhh[HH+tid], b2 = bhh[2*HH+tid];
    float wi0a=Wih[tid*2], wi0b=Wih[tid*2+1];
    float wi1a=Wih[(HH+tid)*2], wi1b=Wih[(HH+tid)*2+1];
    float wi2a=Wih[(2*HH+tid)*2], wi2b=Wih[(2*HH+tid)*2+1];
    float bi0=bih[tid], bi1=bih[HH+tid], bi2=bih[2*HH+tid];
    #pragma unroll
    for (int q = 0; q < 8; q++){
        int r = r0+q;
        int n = r >> 5, b = r & 31;
        const float* x = e + (((size_t)b*TT+t)*NN_+n)*DIN_;
        float x0 = x[0], x1 = x[1];
        float ir = x0*wi0a + x1*wi0b + bi0;
        float iz = x0*wi1a + x1*wi1b + bi1;
        float ig = x0*wi2a + x1*wi2b + bi2;
        float rg = sigf(ir + a0[q] + b0);
        float zg = sigf(iz + a1[q] + b1);
        float ng = tanhf(ig + rg*(a2[q] + b2));
        float hn = (1.f-zg)*ng + zg*hs[q][tid];
        h[r*HH+tid] = hn;
        outs[(((size_t)t*NN_+n)*BB+b)*HH+tid] = hn;
    }
}

__global__ void att_score(const float* __restrict__ outs, const float* __restrict__ attW,
                          const float* __restrict__ attb, const float* __restrict__ wlc,
                          float* __restrict__ z)
{
    int warp = threadIdx.x >> 5, lane = threadIdx.x & 31;
    int row = blockIdx.x*8 + warp;
    if (row >= TT*NB) return;
    const float* o = outs + (size_t)row*HH;
    float o0=o[lane], o1=o[32+lane], o2=o[64+lane], o3=o[96+lane];
    float acc = 0.f;
    for (int d = 0; d < DHH; d++){
        const float* w = attW + d*HH;
        float p = w[lane]*o0 + w[32+lane]*o1 + w[64+lane]*o2 + w[96+lane]*o3;
        p += __shfl_xor_sync(0xffffffffu,p,16);
        p += __shfl_xor_sync(0xffffffffu,p,8);
        p += __shfl_xor_sync(0xffffffffu,p,4);
        p += __shfl_xor_sync(0xffffffffu,p,2);
        p += __shfl_xor_sync(0xffffffffu,p,1);
        acc += wlc[d]*fmaxf(p + attb[d], 0.f);
    }
    if (lane == 0) z[row] = acc;
}

__global__ void att_softmax_t(float* __restrict__ z){
    int idx = blockIdx.x*blockDim.x+threadIdx.x;
    if (idx >= NB) return;
    float v[TT]; float m = -3.0e38f;
    #pragma unroll
    for (int t = 0; t < TT; t++){ v[t] = z[t*NB+idx]; m = fmaxf(m, v[t]); }
    float s = 0.f;
    #pragma unroll
    for (int t = 0; t < TT; t++){ v[t] = expf(v[t]-m); s += v[t]; }
    float inv = 1.f/s;
    #pragma unroll
    for (int t = 0; t < TT; t++) z[t*NB+idx] = v[t]*inv;
}

__global__ void pooled_k(const float* __restrict__ outs, const float* __restrict__ att,
                         float* __restrict__ pooled)
{
    int idx = blockIdx.x*blockDim.x+threadIdx.x;
    if (idx >= NB*HH) return;
    int hh = idx & 127;
    int r = idx >> 7;
    int b = r/NN_, n = r%NN_;
    float acc = 0.f;
    #pragma unroll
    for (int t = 0; t < TT; t++)
        acc += outs[(((size_t)t*NN_+n)*BB+b)*HH+hh] * att[t*NB + n*BB + b];
    pooled[idx] = acc;
}

__global__ void keyqm_k(const float* __restrict__ pooled, const float* __restrict__ wkey,
                        const float* __restrict__ wq, float* __restrict__ keym,
                        float* __restrict__ qm)
{
    int idx = blockIdx.x*blockDim.x+threadIdx.x;
    if (idx >= NB*DHH) return;
    int d = idx % DHH;
    int r = idx / DHH;
    float ak = 0.f, aq = 0.f;
    for (int hh = 0; hh < HH; hh++){
        float p = pooled[r*HH+hh];
        ak += p*wkey[hh*DHH+d];
        aq += p*wq[hh*DHH+d];
    }
    keym[idx] = ak; qm[idx] = aq;
}

__global__ void __launch_bounds__(256) attn_row(
    const float* __restrict__ keym, const float* __restrict__ qm,
    const int* __restrict__ topk, float* __restrict__ adj, float* __restrict__ rowinv)
{
    __shared__ float krow[DHH];
    __shared__ float red[256];
    __shared__ float srt[256];
    const float inv_sqrt_h = 0.08838834764831845f;
    int b = blockIdx.x/NN_, i = blockIdx.x%NN_;
    int tid = threadIdx.x;
    if (tid < DHH) krow[tid] = keym[(b*NN_+i)*DHH+tid];
    __syncthreads();
    float a = -3.0e38f;
    if (tid < NN_){
        const float* q = qm + (b*NN_+tid)*DHH;
        float acc = 0.f;
        #pragma unroll 8
        for (int d = 0; d < DHH; d++) acc += krow[d]*q[d];
        a = acc*inv_sqrt_h;
    }
    red[tid] = a; __syncthreads();
    for (int s = 128; s > 0; s >>= 1){
        if (tid < s) red[tid] = fmaxf(red[tid], red[tid+s]);
        __syncthreads();
    }
    float mx = red[0]; __syncthreads();
    float e = (tid < NN_) ? expf(a-mx) : 0.f;
    red[tid] = e; __syncthreads();
    for (int s = 128; s > 0; s >>= 1){
        if (tid < s) red[tid] += red[tid+s];
        __syncthreads();
    }
    float sum = red[0]; __syncthreads();
    float at = (tid < NN_) ? e/sum : 0.f;
    srt[tid] = (tid < NN_) ? at : -3.0e38f;
    for (int k2 = 2; k2 <= 256; k2 <<= 1){
        for (int j = k2>>1; j > 0; j >>= 1){
            __syncthreads();
            int ixj = tid ^ j;
            if (ixj > tid){
                float x = srt[tid], y = srt[ixj];
                bool asc = ((tid & k2) == 0);
                if ((x > y) == asc){ srt[tid] = y; srt[ixj] = x; }
            }
        }
    }
    __syncthreads();
    int tk = topk ? *topk : 20;
    float kth = srt[256-tk];
    float ad = (tid < NN_ && at >= kth) ? at : 0.f;
    if (tid == i) ad += 1.f;
    if (tid < NN_) adj[(size_t)b*NN2 + i*NN_ + tid] = ad;
    __syncthreads();
    red[tid] = (tid < NN_) ? ad : 0.f;
    __syncthreads();
    for (int s = 128; s > 0; s >>= 1){
        if (tid < s) red[tid] += red[tid+s];
        __syncthreads();
    }
    if (tid == 0){
        float rs = red[0];
        rowinv[b*NN_+i] = (rs == 0.f) ? 0.f : 1.f/rs;
    }
}

__global__ void colsum_k(const float* __restrict__ adj, float* __restrict__ colinv){
    int idx = blockIdx.x*blockDim.x+threadIdx.x;
    if (idx >= NB) return;
    int b = idx/NN_, j = idx%NN_;
    float s = 0.f;
    for (int i = 0; i < NN_; i++) s += adj[(size_t)b*NN2 + i*NN_ + j];
    colinv[idx] = (s == 0.f) ? 0.f : 1.f/s;
}

__global__ void csr_build(const float* __restrict__ adj, const float* __restrict__ rowinv,
                          const float* __restrict__ colinv,
                          int* __restrict__ s1i, float* __restrict__ s1v, int* __restrict__ s1c,
                          int* __restrict__ s2i, float* __restrict__ s2v, int* __restrict__ s2c)
{
    int r = blockIdx.x*blockDim.x+threadIdx.x;
    if (r >= NB) return;
    int b = r/NN_, i = r%NN_;
    const float* A = adj + (size_t)b*NN2;
    int c2 = 0;
    for (int j = 0; j < NN_; j++){
        float a = A[i*NN_+j];
        if (a != 0.f && c2 < CAP2){
            s2i[(size_t)r*CAP2+c2] = j;
            s2v[(size_t)r*CAP2+c2] = a*colinv[b*NN_+j];
            c2++;
        }
    }
    s2c[r] = c2;
    int c1 = 0;
    for (int j = 0; j < NN_; j++){
        float a = A[j*NN_+i];
        if (a != 0.f){
            s1i[(size_t)r*CAP1+c1] = j;
            s1v[(size_t)r*CAP1+c1] = a*rowinv[b*NN_+j];
            c1++;
        }
    }
    s1c[r] = c1;
}

// concat [x, (r*)h] into plane0, columns [dstart, Dc)
__global__ void cat_k(const float* __restrict__ xb, int xbstr, int xnstr, int Dx,
                      const float* __restrict__ h, const float* __restrict__ ru,
                      float* __restrict__ plane0, int Dc, int dstart)
{
    int w = Dc - dstart;
    int idx = blockIdx.x*blockDim.x+threadIdx.x;
    if (idx >= NB*w) return;
    int d = dstart + idx % w;
    int r = idx / w;
    int b = r/NN_, n = r%NN_;
    float v;
    if (d < Dx){
        v = xb[(size_t)b*xbstr + n*xnstr + d];
    } else {
        int dh = d - Dx;
        v = h[r*HH + dh];
        if (ru) v *= ru[r*HH2 + dh];
    }
    plane0[(size_t)r*Dc + d] = v;
}

// sparse spmm: one block per (i, b, support z); thread d computes one output column
__global__ void spmm_sp(
    const float* __restrict__ X1, const float* __restrict__ X2,
    const float* __restrict__ Xprev,
    float* __restrict__ Y1, float* __restrict__ Y2, int D, int dstart)
{
    __shared__ int sj[CAP1];
    __shared__ float sv[CAP1];
    int i = blockIdx.x, b = blockIdx.y, z = blockIdx.z;
    int r = b*NN_ + i;
    const int* Ip; const float* Vp; int cnt; const float* X; float* Y;
    if (z == 0){ Ip = g_s1i + (size_t)r*CAP1; Vp = g_s1v + (size_t)r*CAP1; cnt = g_s1c[r]; X = X1; Y = Y1; }
    else       { Ip = g_s2i + (size_t)r*CAP2; Vp = g_s2v + (size_t)r*CAP2; cnt = g_s2c[r]; X = X2; Y = Y2; }
    for (int k = threadIdx.x; k < cnt; k += blockDim.x){ sj[k] = Ip[k]; sv[k] = Vp[k]; }
    __syncthreads();
    int d = dstart + threadIdx.x;
    if (d >= D) return;
    const float* Xb = X + (size_t)b*NN_*D;
    float acc = 0.f;
    int k = 0;
    for (; k+4 <= cnt; k += 4){
        float a0 = sv[k]  *Xb[sj[k]*D+d];
        float a1 = sv[k+1]*Xb[sj[k+1]*D+d];
        float a2 = sv[k+2]*Xb[sj[k+2]*D+d];
        float a3 = sv[k+3]*Xb[sj[k+3]*D+d];
        acc += (a0+a1)+(a2+a3);
    }
    for (; k < cnt; k++) acc += sv[k]*Xb[sj[k]*D+d];
    float y = acc;
    if (Xprev) y = 2.f*y - Xprev[(size_t)r*D+d];
    Y[(size_t)r*D+d] = y;
}

// 64x64-tile GEMM over 5 planes, f32x2 packed FMA, double-buffered smem staging
// (one barrier per k-slice, staging of slice s+1 overlaps compute of slice s);
// fused epilogue: sigmoid->C or tanh + h update.
__global__ void __launch_bounds__(256) dense_mm(
    const float* __restrict__ Xm, int D,
    const float* __restrict__ Wre, const float* __restrict__ bias,
    int OUT, float* __restrict__ C,
    const float* __restrict__ ruh, float* __restrict__ hbuf)
{
    __shared__ float As[2][16][64];
    __shared__ float Bs[2][16][64];
    int tid = threadIdx.x;
    int row0 = blockIdx.x*64, col0 = blockIdx.y*64;
    int tx = tid & 15, ty = tid >> 4;
    unsigned long long acc[4][2];
    #pragma unroll
    for (int i = 0; i < 4; i++){ acc[i][0] = 0ull; acc[i][1] = 0ull; }
    size_t PL = (size_t)NB*D;
    int nsl = (D + 15) >> 4;
    int S = MM * nsl;

    // staging maps (identical access pattern to proven 16.9ms kernel)
    int a_r  = tid >> 2;          // 0..63
    int a_kb = (tid & 3) * 4;     // 0,4,8,12
    int b_kk = tid >> 4;          // 0..15
    int b_nb = (tid & 15) * 4;    // 0,4,..,60

    auto stage = [&](int m, int k0, int buf){
        const float* Xp = Xm + (size_t)m*PL;
        const float* Wp = Wre + (size_t)m*D*OUT;
        const float* xrow = Xp + (size_t)(row0 + a_r)*D + k0 + a_kb;
        #pragma unroll
        for (int e = 0; e < 4; e++)
            As[buf][a_kb+e][a_r] = (k0 + a_kb + e < D) ? xrow[e] : 0.f;
        if (k0 + b_kk < D){
            const float* wrow = Wp + (size_t)(k0 + b_kk)*OUT + col0 + b_nb;
            #pragma unroll
            for (int e = 0; e < 4; e++)
                Bs[buf][b_kk][b_nb+e] = wrow[e];
        } else {
            #pragma unroll
            for (int e = 0; e < 4; e++)
                Bs[buf][b_kk][b_nb+e] = 0.f;
        }
    };

    stage(0, 0, 0);
    __syncthreads();
    int mn = 0, k0n = 16;
    if (k0n >= D){ k0n = 0; mn = 1; }
    for (int s = 0; s < S; s++){
        int cur = s & 1;
        if (s + 1 < S){
            stage(mn, k0n, cur ^ 1);
            k0n += 16;
            if (k0n >= D){ k0n = 0; mn++; }
        }
        #pragma unroll
        for (int kk = 0; kk < 16; kk++){
            float4 av = *reinterpret_cast<const float4*>(&As[cur][kk][ty*4]);
            const unsigned long long* bp = reinterpret_cast<const unsigned long long*>(&Bs[cur][kk][tx*4]);
            unsigned long long b0 = bp[0], b1 = bp[1];
            unsigned long long a;
            a = pk2(av.x); acc[0][0] = f2fma(a,b0,acc[0][0]); acc[0][1] = f2fma(a,b1,acc[0][1]);
            a = pk2(av.y); acc[1][0] = f2fma(a,b0,acc[1][0]); acc[1][1] = f2fma(a,b1,acc[1][1]);
            a = pk2(av.z); acc[2][0] = f2fma(a,b0,acc[2][0]); acc[2][1] = f2fma(a,b1,acc[2][1]);
            a = pk2(av.w); acc[3][0] = f2fma(a,b0,acc[3][0]); acc[3][1] = f2fma(a,b1,acc[3][1]);
        }
        __syncthreads();
    }
    #pragma unroll
    for (int i = 0; i < 4; i++){
        int rr = row0 + ty*4 + i;
        #pragma unroll
        for (int jp = 0; jp < 2; jp++){
            float2 f = up2(acc[i][jp]);
            #pragma unroll
            for (int u2 = 0; u2 < 2; u2++){
                int cc = col0 + tx*4 + jp*2 + u2;
                float v = (u2 == 0 ? f.x : f.y) + bias[cc];
                if (hbuf){
                    float c = tanhf(v);
                    float u = ruh[(size_t)rr*HH2 + HH + cc];
                    float hold = hbuf[(size_t)rr*HH + cc];
                    hbuf[(size_t)rr*HH + cc] = u*hold + (1.f-u)*c;
                } else {
                    C[(size_t)rr*OUT + cc] = 1.f/(1.f+expf(-v));
                }
            }
        }
    }
}

__global__ void proj_k(const float* __restrict__ h1, const float* __restrict__ pw,
                       const float* __restrict__ pb, float* __restrict__ outp,
                       float* __restrict__ go)
{
    int warp = threadIdx.x >> 5, lane = threadIdx.x & 31;
    int row = blockIdx.x*8 + warp;
    if (row >= NB) return;
    const float* hr = h1 + (size_t)row*HH;
    float a = hr[lane]*pw[lane] + hr[32+lane]*pw[32+lane]
            + hr[64+lane]*pw[64+lane] + hr[96+lane]*pw[96+lane];
    a += __shfl_xor_sync(0xffffffffu,a,16);
    a += __shfl_xor_sync(0xffffffffu,a,8);
    a += __shfl_xor_sync(0xffffffffu,a,4);
    a += __shfl_xor_sync(0xffffffffu,a,2);
    a += __shfl_xor_sync(0xffffffffu,a,1);
    if (lane == 0){
        float v = a + pb[0];
        outp[row] = v;
        go[row] = v;
    }
}

extern "C" void kernel_launch(void* const* d_in, const int* in_sizes, int n_in,
                              void* d_out, int out_size)
{
    const float* enc  = (const float*)d_in[0];
    const float* Wih  = (const float*)d_in[2];
    const float* Whh  = (const float*)d_in[3];
    const float* bih  = (const float*)d_in[4];
    const float* bhh  = (const float*)d_in[5];
    const float* attW = (const float*)d_in[6];
    const float* attb = (const float*)d_in[7];
    const float* wlc  = (const float*)d_in[8];
    const float* wkey = (const float*)d_in[9];
    const float* wq   = (const float*)d_in[10];
    const float* eg0  = (const float*)d_in[11];
    const float* ebg0 = (const float*)d_in[12];
    const float* ec0  = (const float*)d_in[13];
    const float* ebc0 = (const float*)d_in[14];
    const float* eg1  = (const float*)d_in[15];
    const float* ebg1 = (const float*)d_in[16];
    const float* ec1  = (const float*)d_in[17];
    const float* ebc1 = (const float*)d_in[18];
    const float* dg0  = (const float*)d_in[19];
    const float* dbg0 = (const float*)d_in[20];
    const float* dc0  = (const float*)d_in[21];
    const float* dbc0 = (const float*)d_in[22];
    const float* dg1  = (const float*)d_in[23];
    const float* dbg1 = (const float*)d_in[24];
    const float* dc1  = (const float*)d_in[25];
    const float* dbc1 = (const float*)d_in[26];
    const float* pw   = (const float*)d_in[27];
    const float* pb   = (const float*)d_in[28];
    const int*  topk  = (n_in > 29) ? (const int*)d_in[29] : nullptr;
    float* out = (float*)d_out;

    float *wre,*hgru,*outs,*att,*pooled,*keym,*qm,*adj,*rowinv,*colinv,*xm,*rub,*h0,*h1,*go;
    int *s1i,*s1c,*s2i,*s2c; float *s1v,*s2v;
    cudaGetSymbolAddress((void**)&wre, g_Wre);
    cudaGetSymbolAddress((void**)&hgru, g_hgru);
    cudaGetSymbolAddress((void**)&outs, g_outs);
    cudaGetSymbolAddress((void**)&att, g_att);
    cudaGetSymbolAddress((void**)&pooled, g_pooled);
    cudaGetSymbolAddress((void**)&keym, g_keym);
    cudaGetSymbolAddress((void**)&qm, g_qm);
    cudaGetSymbolAddress((void**)&adj, g_adj);
    cudaGetSymbolAddress((void**)&rowinv, g_rowinv);
    cudaGetSymbolAddress((void**)&colinv, g_colinv);
    cudaGetSymbolAddress((void**)&s1i, g_s1i);
    cudaGetSymbolAddress((void**)&s1v, g_s1v);
    cudaGetSymbolAddress((void**)&s1c, g_s1c);
    cudaGetSymbolAddress((void**)&s2i, g_s2i);
    cudaGetSymbolAddress((void**)&s2v, g_s2v);
    cudaGetSymbolAddress((void**)&s2c, g_s2c);
    cudaGetSymbolAddress((void**)&xm, g_xm);
    cudaGetSymbolAddress((void**)&rub, g_ru);
    cudaGetSymbolAddress((void**)&h0, g_h0);
    cudaGetSymbolAddress((void**)&h1, g_h1);
    cudaGetSymbolAddress((void**)&go, g_go);

    transpose_whh<<<(3*HH*HH+255)/256, 256>>>(Whh);
    reorder_w<<<(SZ_EG0+255)/256, 256>>>(eg0, wre+OFF_EG0, D0E, HH2);
    reorder_w<<<(SZ_EC0+255)/256, 256>>>(ec0, wre+OFF_EC0, D0E, HH);
    reorder_w<<<(SZ_EG1+255)/256, 256>>>(eg1, wre+OFF_EG1, D1_, HH2);
    reorder_w<<<(SZ_EC1+255)/256, 256>>>(ec1, wre+OFF_EC1, D1_, HH);
    reorder_w<<<(SZ_DG0+255)/256, 256>>>(dg0, wre+OFF_DG0, D0D, HH2);
    reorder_w<<<(SZ_DC0+255)/256, 256>>>(dc0, wre+OFF_DC0, D0D, HH);
    reorder_w<<<(SZ_EG1+255)/256, 256>>>(dg1, wre+OFF_DG1, D1_, HH2);
    reorder_w<<<(SZ_EC1+255)/256, 256>>>(dc1, wre+OFF_DC1, D1_, HH);

    zero_k<<<(NB*HH+255)/256, 256>>>(hgru, NB*HH);
    for (int t = 0; t < TT; t++)
        gru_step<<<NB/8, 128>>>(enc, t, Wih, bih, bhh, hgru, outs);

    att_score<<<(TT*NB)/8, 256>>>(outs, attW, attb, wlc, att);
    att_softmax_t<<<(NB+255)/256, 256>>>(att);
    pooled_k<<<(NB*HH+255)/256, 256>>>(outs, att, pooled);
    keyqm_k<<<(NB*DHH+255)/256, 256>>>(pooled, wkey, wq, keym, qm);
    attn_row<<<BB*NN_, 256>>>(keym, qm, topk, adj, rowinv);
    colsum_k<<<(NB+255)/256, 256>>>(adj, colinv);
    csr_build<<<(NB+255)/256, 256>>>(adj, rowinv, colinv, s1i, s1v, s1c, s2i, s2v, s2c);

    auto gconv = [&](const float* xb, int xbstr, int xnstr, int Dx, float* h,
                     const float* rmul, const float* Wp, const float* bias,
                     int OUT, float* Cout, float* hfuse){
        int Dc = Dx + HH;
        size_t PL = (size_t)NB*Dc;
        int dstart = rmul ? Dx : 0;     // candidate pass reuses gate's x-column planes
        int w = Dc - dstart;
        cat_k<<<(NB*w+255)/256, 256>>>(xb, xbstr, xnstr, Dx, h, rmul, xm, Dc, dstart);
        int nt = ((w+31)/32)*32; if (nt > 256) nt = 256;
        dim3 sg(NN_, BB, 2);
        spmm_sp<<<sg, nt>>>(xm, xm, nullptr, xm+PL, xm+3*PL, Dc, dstart);
        spmm_sp<<<sg, nt>>>(xm+PL, xm+3*PL, xm, xm+2*PL, xm+4*PL, Dc, dstart);
        dense_mm<<<dim3(NB/64, OUT/64), 256>>>(xm, Dc, Wp, bias, OUT, Cout, rmul, hfuse);
    };
    auto cell = [&](const float* xb, int xbstr, int xnstr, int Dx, float* h,
                    const float* Wg, const float* bg, const float* Wc, const float* bc){
        gconv(xb, xbstr, xnstr, Dx, h, nullptr, Wg, bg, HH2, rub, nullptr);
        gconv(xb, xbstr, xnstr, Dx, h, rub,     Wc, bc, HH,  nullptr, h);
    };

    zero_k<<<(NB*HH+255)/256, 256>>>(h0, NB*HH);
    zero_k<<<(NB*HH+255)/256, 256>>>(h1, NB*HH);
    for (int t = 0; t < TT; t++){
        cell(enc + (size_t)t*NN_*DIN_, TT*NN_*DIN_, DIN_, DIN_, h0,
             wre+OFF_EG0, ebg0, wre+OFF_EC0, ebc0);
        cell(h0, NN_*HH, HH, HH, h1,
             wre+OFF_EG1, ebg1, wre+OFF_EC1, ebc1);
    }

    zero_k<<<(NB+255)/256, 256>>>(go, NB);
    for (int t = 0; t < TT; t++){
        cell(go, NN_, 1, 1, h0,
             wre+OFF_DG0, dbg0, wre+OFF_DC0, dbc0);
        cell(h0, NN_*HH, HH, HH, h1,
             wre+OFF_DG1, dbg1, wre+OFF_DC1, dbc1);
        proj_k<<<NB/8, 256>>>(h1, pw, pb, out + (size_t)t*NB, go);
    }
    (void)in_sizes; (void)out_size;
}